// round 9
// baseline (speedup 1.0000x reference)
#include <cuda_runtime.h>
#include <cuda_fp16.h>
#include <cstdint>

#define SEQ   2048
#define BATCH 4
#define NTOK  (SEQ * BATCH)      // 8192
#define DIM   1024
#define NH    16
#define HD    64

// ---------------- scratch (device globals per allocation rules) -------------
__device__ float  g_xpe [NTOK * DIM];     // fp32 residual for LN
__device__ float  g_proj[NTOK * DIM];     // fp32 O-projection for LN
__device__ __half g_xh  [NTOK * DIM];     // half x+pe (GEMM A)
__device__ __half g_qh  [NTOK * DIM];
__device__ __half g_kh  [NTOK * DIM];
__device__ __half g_vh  [NTOK * DIM];
__device__ __half g_ah  [NTOK * DIM];     // attention output (half)
__device__ __half g_wTh [4][DIM * DIM];   // transposed weights [N][K], half

// ---------------- helpers -----------------------------------------------------
__device__ __forceinline__ uint32_t smem_u32(const void* p) {
    uint32_t a;
    asm("{ .reg .u64 t; cvta.to.shared.u64 t, %1; cvt.u32.u64 %0, t; }" : "=r"(a) : "l"(p));
    return a;
}
__device__ __forceinline__ void cp16(uint32_t dst, const void* src) {
    asm volatile("cp.async.cg.shared.global [%0], [%1], 16;" :: "r"(dst), "l"(src));
}
#define CP_COMMIT() asm volatile("cp.async.commit_group;" ::: "memory")
#define CP_WAIT0()  asm volatile("cp.async.wait_group 0;" ::: "memory")

__device__ __forceinline__ void mma_f16(float* d, const uint32_t* a, const uint32_t* b) {
    asm volatile(
        "mma.sync.aligned.m16n8k16.row.col.f32.f16.f16.f32 "
        "{%0,%1,%2,%3}, {%4,%5,%6,%7}, {%8,%9}, {%0,%1,%2,%3};\n"
        : "+f"(d[0]), "+f"(d[1]), "+f"(d[2]), "+f"(d[3])
        : "r"(a[0]), "r"(a[1]), "r"(a[2]), "r"(a[3]), "r"(b[0]), "r"(b[1]));
}
__device__ __forceinline__ uint32_t packh(__half x, __half y) {
    __half2 t = __halves2half2(x, y);
    return *(uint32_t*)&t;
}
__device__ __forceinline__ uint32_t packf(float x, float y) {
    __half2 t = __floats2half2_rn(x, y);
    return *(uint32_t*)&t;
}
// swizzled half-index within a 64-half-wide tile: rows 128B, chunk^row&7
__device__ __forceinline__ int swadr(int row, int c) {
    return row * 64 + ((((c >> 3) ^ (row & 7))) << 3) + (c & 7);
}
// physical half-offset for storing 16B chunk c8 (0..7) of row r
__device__ __forceinline__ int swst(int r, int c8) {
    return r * 64 + ((c8 ^ (r & 7)) << 3);
}

// ---------------- x + pe (fp32 out + half out) -------------------------------
__global__ void k_addpe(const float* __restrict__ x, const float* __restrict__ pe) {
    int idx = blockIdx.x * 256 + threadIdx.x;        // float4 index
    const float4* x4  = (const float4*)x;
    const float4* pe4 = (const float4*)pe;
    float4*       o4  = (float4*)g_xpe;
    int row = idx >> 8;
    int c   = idx & 255;
    int s   = row & (SEQ - 1);
    float4 a = x4[idx];
    float4 b = pe4[s * 256 + c];
    a.x += b.x; a.y += b.y; a.z += b.z; a.w += b.w;
    o4[idx] = a;
    uint2 hp;
    hp.x = packf(a.x, a.y);
    hp.y = packf(a.z, a.w);
    *(uint2*)&g_xh[(size_t)idx * 4] = hp;
}

// ---------------- fused weight transpose -> half ------------------------------
__global__ __launch_bounds__(256) void k_transpose4(
    const float* __restrict__ w0, const float* __restrict__ w1,
    const float* __restrict__ w2, const float* __restrict__ w3)
{
    __shared__ float t[32][33];
    const float* in;
    switch (blockIdx.z) {
        case 0: in = w0; break;
        case 1: in = w1; break;
        case 2: in = w2; break;
        default: in = w3; break;
    }
    __half* out = g_wTh[blockIdx.z];
    int n0 = blockIdx.x * 32, k0 = blockIdx.y * 32;
    int tx = threadIdx.x & 31, ty = threadIdx.x >> 5;
    #pragma unroll
    for (int i = ty; i < 32; i += 8)
        t[i][tx] = in[(size_t)(k0 + i) * DIM + n0 + tx];
    __syncthreads();
    #pragma unroll
    for (int i = ty; i < 32; i += 8)
        out[(size_t)(n0 + i) * DIM + k0 + tx] = __float2half(t[tx][i]);
}

// ---------------- fp16 mma GEMM: C[M,N] = A[M,K] @ Bt[N,K]^T + bias ----------
// 128x128 CTA tile, BK=64 halves, 8 warps (4x2), XOR-swizzled smem (64 KB).
#define TILEH (128 * 64)                    // 8192 halves = 16384 B per tile
#define GSMEM (4 * TILEH * 2)               // 65536 bytes
#define NCH   (DIM / 64)                    // 16 stages

template <typename OutT>
__global__ __launch_bounds__(256) void k_gemm_h(
    const __half* __restrict__ A, const __half* __restrict__ Bt,
    const float* __restrict__ bias, OutT* __restrict__ C)
{
    extern __shared__ __half smh[];
    const uint32_t smb = smem_u32(smh);
    const int tid  = threadIdx.x;
    const int lane = tid & 31;
    const int wid  = tid >> 5;
    const int wr   = wid & 3;
    const int wc   = wid >> 2;
    const int j    = lane & 3;
    const int rowBase = blockIdx.y * 128;
    const int colBase = blockIdx.x * 128;

    const __half* Ab = A  + (size_t)rowBase * DIM;
    const __half* Bb = Bt + (size_t)colBase * DIM;

    float acc[2][8][4];
    #pragma unroll
    for (int mt = 0; mt < 2; mt++)
        #pragma unroll
        for (int nt = 0; nt < 8; nt++)
            #pragma unroll
            for (int q = 0; q < 4; q++) acc[mt][nt][q] = 0.f;

    auto copy_tile = [&](int buf, int chunk) {
        uint32_t as_ = smb + buf * 2 * TILEH * 2;
        uint32_t bs_ = as_ + TILEH * 2;
        #pragma unroll
        for (int i = 0; i < 4; i++) {
            int idx = i * 256 + tid;        // 0..1023
            int r = idx >> 3, c8 = idx & 7;
            uint32_t off = (uint32_t)swst(r, c8) * 2;
            cp16(as_ + off, Ab + (size_t)r * DIM + chunk * 64 + c8 * 8);
            cp16(bs_ + off, Bb + (size_t)r * DIM + chunk * 64 + c8 * 8);
        }
    };
    auto compute = [&](int buf) {
        const __half* as_ = smh + buf * 2 * TILEH;
        const __half* bs_ = as_ + TILEH;
        #pragma unroll
        for (int kk = 0; kk < 64; kk += 16) {
            uint32_t af[2][4];
            #pragma unroll
            for (int mt = 0; mt < 2; mt++) {
                int r = wr * 32 + mt * 16 + (lane >> 2);
                int c = kk + 2 * j;
                af[mt][0] = *(const uint32_t*)&as_[swadr(r, c)];
                af[mt][1] = *(const uint32_t*)&as_[swadr(r + 8, c)];
                af[mt][2] = *(const uint32_t*)&as_[swadr(r, c + 8)];
                af[mt][3] = *(const uint32_t*)&as_[swadr(r + 8, c + 8)];
            }
            #pragma unroll
            for (int nt = 0; nt < 8; nt++) {
                int n = wc * 64 + nt * 8 + (lane >> 2);
                uint32_t bf[2];
                bf[0] = *(const uint32_t*)&bs_[swadr(n, kk + 2 * j)];
                bf[1] = *(const uint32_t*)&bs_[swadr(n, kk + 2 * j + 8)];
                mma_f16(acc[0][nt], af[0], bf);
                mma_f16(acc[1][nt], af[1], bf);
            }
        }
    };

    copy_tile(0, 0); CP_COMMIT();
    CP_WAIT0(); __syncthreads();
    for (int c = 0; c < NCH; c++) {
        int b = c & 1;
        if (c + 1 < NCH) { copy_tile(b ^ 1, c + 1); CP_COMMIT(); }
        compute(b);
        CP_WAIT0(); __syncthreads();
    }

    #pragma unroll
    for (int mt = 0; mt < 2; mt++) {
        int r = rowBase + wr * 32 + mt * 16 + (lane >> 2);
        #pragma unroll
        for (int nt = 0; nt < 8; nt++) {
            int col = colBase + wc * 64 + nt * 8 + 2 * j;
            float2 b2 = *(const float2*)&bias[col];
            float o00 = acc[mt][nt][0] + b2.x, o01 = acc[mt][nt][1] + b2.y;
            float o10 = acc[mt][nt][2] + b2.x, o11 = acc[mt][nt][3] + b2.y;
            if constexpr (sizeof(OutT) == 2) {
                *(uint32_t*)&C[(size_t)r * DIM + col]       = packf(o00, o01);
                *(uint32_t*)&C[(size_t)(r + 8) * DIM + col] = packf(o10, o11);
            } else {
                *(float2*)&C[(size_t)r * DIM + col]       = make_float2(o00, o01);
                *(float2*)&C[(size_t)(r + 8) * DIM + col] = make_float2(o10, o11);
            }
        }
    }
}

// ---------------- flash attention, fp16 mma ----------------------------------
// 256 threads / 8 warps, 128 queries per CTA; warp owns 16 q-rows.
// XOR-swizzled smem (49 KB); K+V double-buffered; P stays in registers.
#define QTILE   (128 * 64)                 // 8192 halves
#define KVTILE  (64 * 64)                  // 4096 halves
#define OFFK(b) (QTILE + (b) * 2 * KVTILE)
#define OFFV(b) (QTILE + (b) * 2 * KVTILE + KVTILE)
#define ASMEM   ((QTILE + 4 * KVTILE) * 2) // 49152 bytes
#define NT      (SEQ / 64)
#define SCL     0.18033688011112042f       // 0.125 * log2(e)

__global__ __launch_bounds__(256) void k_attn_h()
{
    extern __shared__ __half smh[];
    const uint32_t smb = smem_u32(smh);

    const int tid  = threadIdx.x;
    const int lane = tid & 31;
    const int wid  = tid >> 5;
    const int j    = lane & 3;
    const int qt = blockIdx.x, h = blockIdx.y, b = blockIdx.z;
    const size_t qbase  = (size_t)(b * SEQ + qt * 128);
    const size_t kvbase = (size_t)(b * SEQ) * DIM + h * 64;

    auto copy_q = [&]() {
        #pragma unroll
        for (int i = 0; i < 4; i++) {
            int idx = i * 256 + tid;        // 1024 = 128 rows x 8 chunks
            int r = idx >> 3, c8 = idx & 7;
            cp16(smb + (uint32_t)swst(r, c8) * 2,
                 g_qh + (qbase + r) * DIM + h * 64 + c8 * 8);
        }
    };
    auto copy_kv = [&](int buf, int kt) {
        uint32_t kb = smb + OFFK(buf) * 2;
        uint32_t vb = smb + OFFV(buf) * 2;
        #pragma unroll
        for (int i = 0; i < 2; i++) {
            int idx = i * 256 + tid;        // 512 = 64 rows x 8 chunks
            int r = idx >> 3, c8 = idx & 7;
            size_t g = kvbase + (size_t)(kt * 64 + r) * DIM + c8 * 8;
            uint32_t off = (uint32_t)swst(r, c8) * 2;
            cp16(kb + off, g_kh + g);
            cp16(vb + off, g_vh + g);
        }
    };

    float Oa[8][4];
    #pragma unroll
    for (int nt = 0; nt < 8; nt++)
        #pragma unroll
        for (int q = 0; q < 4; q++) Oa[nt][q] = 0.f;
    float m0 = -1e30f, m1 = -1e30f, l0 = 0.f, l1 = 0.f;  // log2 domain

    copy_q(); copy_kv(0, 0); CP_COMMIT();
    CP_WAIT0(); __syncthreads();

    for (int kt = 0; kt < NT; kt++) {
        int bu = kt & 1;
        if (kt + 1 < NT) { copy_kv(bu ^ 1, kt + 1); CP_COMMIT(); }

        const __half* Qs = smh;
        const __half* Ks = smh + OFFK(bu);
        const __half* Vs = smh + OFFV(bu);

        // ---- S = Q @ K^T ----
        float Sa[8][4];
        #pragma unroll
        for (int nt = 0; nt < 8; nt++)
            #pragma unroll
            for (int q = 0; q < 4; q++) Sa[nt][q] = 0.f;
        #pragma unroll
        for (int kk = 0; kk < 64; kk += 16) {
            uint32_t af[4];
            int r = wid * 16 + (lane >> 2);
            int c = kk + 2 * j;
            af[0] = *(const uint32_t*)&Qs[swadr(r, c)];
            af[1] = *(const uint32_t*)&Qs[swadr(r + 8, c)];
            af[2] = *(const uint32_t*)&Qs[swadr(r, c + 8)];
            af[3] = *(const uint32_t*)&Qs[swadr(r + 8, c + 8)];
            #pragma unroll
            for (int nt = 0; nt < 8; nt++) {
                int n = nt * 8 + (lane >> 2);
                uint32_t bf[2];
                bf[0] = *(const uint32_t*)&Ks[swadr(n, c)];
                bf[1] = *(const uint32_t*)&Ks[swadr(n, c + 8)];
                mma_f16(Sa[nt], af, bf);
            }
        }

        // ---- online softmax (exp2 domain) ----
        #pragma unroll
        for (int nt = 0; nt < 8; nt++)
            #pragma unroll
            for (int q = 0; q < 4; q++) Sa[nt][q] *= SCL;

        float mx0 = m0, mx1 = m1;
        #pragma unroll
        for (int nt = 0; nt < 8; nt++) {
            mx0 = fmaxf(mx0, fmaxf(Sa[nt][0], Sa[nt][1]));
            mx1 = fmaxf(mx1, fmaxf(Sa[nt][2], Sa[nt][3]));
        }
        #pragma unroll
        for (int o = 1; o <= 2; o <<= 1) {
            mx0 = fmaxf(mx0, __shfl_xor_sync(0xffffffffu, mx0, o));
            mx1 = fmaxf(mx1, __shfl_xor_sync(0xffffffffu, mx1, o));
        }
        float corr0 = exp2f(m0 - mx0);
        float corr1 = exp2f(m1 - mx1);
        m0 = mx0; m1 = mx1;

        float s0 = 0.f, s1 = 0.f;
        #pragma unroll
        for (int nt = 0; nt < 8; nt++) {
            Sa[nt][0] = exp2f(Sa[nt][0] - m0);
            Sa[nt][1] = exp2f(Sa[nt][1] - m0);
            Sa[nt][2] = exp2f(Sa[nt][2] - m1);
            Sa[nt][3] = exp2f(Sa[nt][3] - m1);
            s0 += Sa[nt][0] + Sa[nt][1];
            s1 += Sa[nt][2] + Sa[nt][3];
        }
        #pragma unroll
        for (int o = 1; o <= 2; o <<= 1) {
            s0 += __shfl_xor_sync(0xffffffffu, s0, o);
            s1 += __shfl_xor_sync(0xffffffffu, s1, o);
        }
        l0 = l0 * corr0 + s0;
        l1 = l1 * corr1 + s1;
        #pragma unroll
        for (int nt = 0; nt < 8; nt++) {
            Oa[nt][0] *= corr0; Oa[nt][1] *= corr0;
            Oa[nt][2] *= corr1; Oa[nt][3] *= corr1;
        }

        // ---- O += P @ V  (A-frags = local packs of Sa) ----
        #pragma unroll
        for (int kk2 = 0; kk2 < 4; kk2++) {
            uint32_t af[4];
            af[0] = packf(Sa[2 * kk2][0],     Sa[2 * kk2][1]);
            af[1] = packf(Sa[2 * kk2][2],     Sa[2 * kk2][3]);
            af[2] = packf(Sa[2 * kk2 + 1][0], Sa[2 * kk2 + 1][1]);
            af[3] = packf(Sa[2 * kk2 + 1][2], Sa[2 * kk2 + 1][3]);
            int krow = kk2 * 16 + 2 * j;
            #pragma unroll
            for (int nt = 0; nt < 8; nt++) {
                int n = nt * 8 + (lane >> 2);
                uint32_t bf[2];
                bf[0] = packh(Vs[swadr(krow, n)],     Vs[swadr(krow + 1, n)]);
                bf[1] = packh(Vs[swadr(krow + 8, n)], Vs[swadr(krow + 9, n)]);
                mma_f16(Oa[nt], af, bf);
            }
        }

        CP_WAIT0(); __syncthreads();
    }

    float inv0 = 1.f / l0, inv1 = 1.f / l1;
    size_t r = qbase + wid * 16 + (lane >> 2);
    #pragma unroll
    for (int nt = 0; nt < 8; nt++) {
        int col = h * 64 + nt * 8 + 2 * j;
        *(uint32_t*)&g_ah[r * DIM + col] =
            packf(Oa[nt][0] * inv0, Oa[nt][1] * inv0);
        *(uint32_t*)&g_ah[(r + 8) * DIM + col] =
            packf(Oa[nt][2] * inv1, Oa[nt][3] * inv1);
    }
}

// ---------------- residual + layernorm ---------------------------------------
__global__ __launch_bounds__(256) void k_ln(const float* __restrict__ gamma,
                                            const float* __restrict__ beta,
                                            float* __restrict__ out)
{
    __shared__ float ws[8], wss[8];
    const int row = blockIdx.x;
    const int tid = threadIdx.x;

    const float4* p4 = (const float4*)(g_proj + (size_t)row * DIM);
    const float4* x4 = (const float4*)(g_xpe  + (size_t)row * DIM);
    float4 a = p4[tid];
    float4 b = x4[tid];
    float4 hv = make_float4(a.x + b.x, a.y + b.y, a.z + b.z, a.w + b.w);

    float s  = hv.x + hv.y + hv.z + hv.w;
    float ss = hv.x * hv.x + hv.y * hv.y + hv.z * hv.z + hv.w * hv.w;
    #pragma unroll
    for (int o = 16; o; o >>= 1) {
        s  += __shfl_xor_sync(0xffffffffu, s,  o);
        ss += __shfl_xor_sync(0xffffffffu, ss, o);
    }
    int w = tid >> 5;
    if ((tid & 31) == 0) { ws[w] = s; wss[w] = ss; }
    __syncthreads();

    float ts = 0.f, tss = 0.f;
    #pragma unroll
    for (int i = 0; i < 8; i++) { ts += ws[i]; tss += wss[i]; }
    float mean = ts * (1.f / 1024.f);
    float var  = tss * (1.f / 1024.f) - mean * mean;
    float rstd = rsqrtf(var + 1e-5f);

    float4 g  = ((const float4*)gamma)[tid];
    float4 be = ((const float4*)beta)[tid];
    float4 o;
    o.x = (hv.x - mean) * rstd * g.x + be.x;
    o.y = (hv.y - mean) * rstd * g.y + be.y;
    o.z = (hv.z - mean) * rstd * g.z + be.z;
    o.w = (hv.w - mean) * rstd * g.w + be.w;
    ((float4*)out)[(size_t)row * 256 + tid] = o;
}

// ---------------- launch ------------------------------------------------------
extern "C" void kernel_launch(void* const* d_in, const int* in_sizes, int n_in,
                              void* d_out, int out_size)
{
    const float* x     = (const float*)d_in[0];
    const float* wq    = (const float*)d_in[1];
    const float* bq    = (const float*)d_in[2];
    const float* wk    = (const float*)d_in[3];
    const float* bk    = (const float*)d_in[4];
    const float* wv    = (const float*)d_in[5];
    const float* bv    = (const float*)d_in[6];
    const float* wo    = (const float*)d_in[7];
    const float* bo    = (const float*)d_in[8];
    const float* gamma = (const float*)d_in[9];
    const float* beta  = (const float*)d_in[10];
    const float* pe    = (const float*)d_in[11];
    float* out = (float*)d_out;

    void *pxh, *pqh, *pkh, *pvh, *pah, *pproj, *pwTh;
    cudaGetSymbolAddress(&pxh,   g_xh);
    cudaGetSymbolAddress(&pqh,   g_qh);
    cudaGetSymbolAddress(&pkh,   g_kh);
    cudaGetSymbolAddress(&pvh,   g_vh);
    cudaGetSymbolAddress(&pah,   g_ah);
    cudaGetSymbolAddress(&pproj, g_proj);
    cudaGetSymbolAddress(&pwTh,  g_wTh);
    __half* wTh = (__half*)pwTh;

    cudaFuncSetAttribute(k_gemm_h<__half>, cudaFuncAttributeMaxDynamicSharedMemorySize, GSMEM);
    cudaFuncSetAttribute(k_gemm_h<float>,  cudaFuncAttributeMaxDynamicSharedMemorySize, GSMEM);
    cudaFuncSetAttribute(k_attn_h, cudaFuncAttributeMaxDynamicSharedMemorySize, ASMEM);

    k_addpe<<<(NTOK * DIM / 4) / 256, 256>>>(x, pe);

    dim3 tgrid(DIM / 32, DIM / 32, 4);
    k_transpose4<<<tgrid, 256>>>(wq, wk, wv, wo);

    dim3 ggrid(DIM / 128, NTOK / 128);           // (8, 64)
    k_gemm_h<__half><<<ggrid, 256, GSMEM>>>((const __half*)pxh, wTh + 0 * DIM * DIM, bq, (__half*)pqh);
    k_gemm_h<__half><<<ggrid, 256, GSMEM>>>((const __half*)pxh, wTh + 1 * DIM * DIM, bk, (__half*)pkh);
    k_gemm_h<__half><<<ggrid, 256, GSMEM>>>((const __half*)pxh, wTh + 2 * DIM * DIM, bv, (__half*)pvh);

    dim3 agrid(SEQ / 128, NH, BATCH);            // (16, 16, 4)
    k_attn_h<<<agrid, 256, ASMEM>>>();

    k_gemm_h<float><<<ggrid, 256, GSMEM>>>((const __half*)pah, wTh + 3 * DIM * DIM, bo, (float*)pproj);

    k_ln<<<NTOK, 256>>>(gamma, beta, out);
}

// round 10
// speedup vs baseline: 1.1603x; 1.1603x over previous
#include <cuda_runtime.h>
#include <cuda_fp16.h>
#include <cstdint>

#define SEQ   2048
#define BATCH 4
#define NTOK  (SEQ * BATCH)      // 8192
#define DIM   1024
#define NH    16
#define HD    64

// ---------------- scratch (device globals per allocation rules) -------------
__device__ float  g_xpe [NTOK * DIM];     // fp32 residual for LN
__device__ float  g_proj[NTOK * DIM];     // fp32 O-projection for LN
__device__ __half g_xh  [NTOK * DIM];     // half x+pe (GEMM A)
__device__ __half g_qh  [NTOK * DIM];
__device__ __half g_kh  [NTOK * DIM];
__device__ __half g_vh  [NTOK * DIM];
__device__ __half g_ah  [NTOK * DIM];     // attention output (half)
__device__ __half g_wTh [4][DIM * DIM];   // transposed weights [N][K], half

// ---------------- helpers -----------------------------------------------------
__device__ __forceinline__ uint32_t smem_u32(const void* p) {
    uint32_t a;
    asm("{ .reg .u64 t; cvta.to.shared.u64 t, %1; cvt.u32.u64 %0, t; }" : "=r"(a) : "l"(p));
    return a;
}
__device__ __forceinline__ void cp16(uint32_t dst, const void* src) {
    asm volatile("cp.async.cg.shared.global [%0], [%1], 16;" :: "r"(dst), "l"(src));
}
#define CP_COMMIT() asm volatile("cp.async.commit_group;" ::: "memory")
#define CP_WAIT0()  asm volatile("cp.async.wait_group 0;" ::: "memory")
#define CP_WAIT1()  asm volatile("cp.async.wait_group 1;" ::: "memory")

__device__ __forceinline__ void mma_f16(float* d, const uint32_t* a, const uint32_t* b) {
    asm volatile(
        "mma.sync.aligned.m16n8k16.row.col.f32.f16.f16.f32 "
        "{%0,%1,%2,%3}, {%4,%5,%6,%7}, {%8,%9}, {%0,%1,%2,%3};\n"
        : "+f"(d[0]), "+f"(d[1]), "+f"(d[2]), "+f"(d[3])
        : "r"(a[0]), "r"(a[1]), "r"(a[2]), "r"(a[3]), "r"(b[0]), "r"(b[1]));
}
__device__ __forceinline__ uint32_t packh(__half x, __half y) {
    __half2 t = __halves2half2(x, y);
    return *(uint32_t*)&t;
}
__device__ __forceinline__ uint32_t packf(float x, float y) {
    __half2 t = __floats2half2_rn(x, y);
    return *(uint32_t*)&t;
}

// ---------------- x + pe (fp32 out + half out) -------------------------------
__global__ void k_addpe(const float* __restrict__ x, const float* __restrict__ pe) {
    int idx = blockIdx.x * 256 + threadIdx.x;        // float4 index
    const float4* x4  = (const float4*)x;
    const float4* pe4 = (const float4*)pe;
    float4*       o4  = (float4*)g_xpe;
    int row = idx >> 8;
    int c   = idx & 255;
    int s   = row & (SEQ - 1);
    float4 a = x4[idx];
    float4 b = pe4[s * 256 + c];
    a.x += b.x; a.y += b.y; a.z += b.z; a.w += b.w;
    o4[idx] = a;
    uint2 hp;
    hp.x = packf(a.x, a.y);
    hp.y = packf(a.z, a.w);
    *(uint2*)&g_xh[(size_t)idx * 4] = hp;
}

// ---------------- fused weight transpose -> half ------------------------------
__global__ __launch_bounds__(256) void k_transpose4(
    const float* __restrict__ w0, const float* __restrict__ w1,
    const float* __restrict__ w2, const float* __restrict__ w3)
{
    __shared__ float t[32][33];
    const float* in;
    switch (blockIdx.z) {
        case 0: in = w0; break;
        case 1: in = w1; break;
        case 2: in = w2; break;
        default: in = w3; break;
    }
    __half* out = g_wTh[blockIdx.z];
    int n0 = blockIdx.x * 32, k0 = blockIdx.y * 32;
    int tx = threadIdx.x & 31, ty = threadIdx.x >> 5;
    #pragma unroll
    for (int i = ty; i < 32; i += 8)
        t[i][tx] = in[(size_t)(k0 + i) * DIM + n0 + tx];
    __syncthreads();
    #pragma unroll
    for (int i = ty; i < 32; i += 8)
        out[(size_t)(n0 + i) * DIM + k0 + tx] = __float2half(t[tx][i]);
}

// ---------------- fp16 mma GEMM: C[M,N] = A[M,K] @ Bt[N,K]^T + bias ----------
// 128x128 CTA tile, BK=64 halves, 8 warps (4x2), padded smem, 3-stage pipeline.
// blockIdx.z selects weight/bias/output (QKV fusion); z-extent 1 for O-proj.
#define GPADH 72
#define TILEH (128 * GPADH)                 // halves per operand tile
#define STAGEB (2 * TILEH * 2)              // bytes per stage (A+B) = 36864
#define GSMEM (3 * STAGEB)                  // 110592 bytes
#define NCH   (DIM / 64)                    // 16 stages

template <typename OutT>
__global__ __launch_bounds__(256) void k_gemm_h(
    const __half* __restrict__ A,
    const __half* __restrict__ Bt0, const __half* __restrict__ Bt1, const __half* __restrict__ Bt2,
    const float* __restrict__ bi0,  const float* __restrict__ bi1,  const float* __restrict__ bi2,
    OutT* __restrict__ C0, OutT* __restrict__ C1, OutT* __restrict__ C2)
{
    extern __shared__ __half smh[];
    const uint32_t smb = smem_u32(smh);
    const int tid  = threadIdx.x;
    const int lane = tid & 31;
    const int wid  = tid >> 5;
    const int wr   = wid & 3;
    const int wc   = wid >> 2;
    const int j    = lane & 3;
    const int rowBase = blockIdx.y * 128;
    const int colBase = blockIdx.x * 128;

    const __half* Bt   = (blockIdx.z == 0) ? Bt0 : (blockIdx.z == 1) ? Bt1 : Bt2;
    const float*  bias = (blockIdx.z == 0) ? bi0 : (blockIdx.z == 1) ? bi1 : bi2;
    OutT*         C    = (blockIdx.z == 0) ? C0  : (blockIdx.z == 1) ? C1  : C2;

    const __half* Ab = A  + (size_t)rowBase * DIM;
    const __half* Bb = Bt + (size_t)colBase * DIM;

    float acc[2][8][4];
    #pragma unroll
    for (int mt = 0; mt < 2; mt++)
        #pragma unroll
        for (int nt = 0; nt < 8; nt++)
            #pragma unroll
            for (int q = 0; q < 4; q++) acc[mt][nt][q] = 0.f;

    auto copy_tile = [&](int buf, int chunk) {
        uint32_t as_ = smb + buf * STAGEB;
        uint32_t bs_ = as_ + TILEH * 2;
        #pragma unroll
        for (int i = 0; i < 4; i++) {
            int idx = i * 256 + tid;        // 0..1023
            int r = idx >> 3, c8 = idx & 7; // row, 8-half chunk
            uint32_t off = (r * GPADH + c8 * 8) * 2;
            cp16(as_ + off, Ab + (size_t)r * DIM + chunk * 64 + c8 * 8);
            cp16(bs_ + off, Bb + (size_t)r * DIM + chunk * 64 + c8 * 8);
        }
    };
    auto compute = [&](int buf) {
        const __half* as_ = smh + buf * (STAGEB / 2);
        const __half* bs_ = as_ + TILEH;
        #pragma unroll
        for (int kk = 0; kk < 64; kk += 16) {
            uint32_t af[2][4];
            #pragma unroll
            for (int mt = 0; mt < 2; mt++) {
                int r = wr * 32 + mt * 16 + (lane >> 2);
                int c = kk + 2 * j;
                af[mt][0] = *(const uint32_t*)&as_[r * GPADH + c];
                af[mt][1] = *(const uint32_t*)&as_[(r + 8) * GPADH + c];
                af[mt][2] = *(const uint32_t*)&as_[r * GPADH + c + 8];
                af[mt][3] = *(const uint32_t*)&as_[(r + 8) * GPADH + c + 8];
            }
            #pragma unroll
            for (int nt = 0; nt < 8; nt++) {
                int n = wc * 64 + nt * 8 + (lane >> 2);
                uint32_t bf[2];
                bf[0] = *(const uint32_t*)&bs_[n * GPADH + kk + 2 * j];
                bf[1] = *(const uint32_t*)&bs_[n * GPADH + kk + 2 * j + 8];
                mma_f16(acc[0][nt], af[0], bf);
                mma_f16(acc[1][nt], af[1], bf);
            }
        }
    };

    // 3-stage pipeline; always commit one group per iteration (possibly empty)
    copy_tile(0, 0); CP_COMMIT();
    copy_tile(1, 1); CP_COMMIT();
    int buf = 0;
    for (int c = 0; c < NCH; c++) {
        CP_WAIT1();                         // oldest group (stage c) done
        __syncthreads();
        if (c + 2 < NCH) copy_tile((buf + 2) % 3, c + 2);
        CP_COMMIT();
        compute(buf);
        buf = (buf + 1) % 3;
    }

    #pragma unroll
    for (int mt = 0; mt < 2; mt++) {
        int r = rowBase + wr * 32 + mt * 16 + (lane >> 2);
        #pragma unroll
        for (int nt = 0; nt < 8; nt++) {
            int col = colBase + wc * 64 + nt * 8 + 2 * j;
            float2 b2 = *(const float2*)&bias[col];
            float o00 = acc[mt][nt][0] + b2.x, o01 = acc[mt][nt][1] + b2.y;
            float o10 = acc[mt][nt][2] + b2.x, o11 = acc[mt][nt][3] + b2.y;
            if constexpr (sizeof(OutT) == 2) {
                *(uint32_t*)&C[(size_t)r * DIM + col]       = packf(o00, o01);
                *(uint32_t*)&C[(size_t)(r + 8) * DIM + col] = packf(o10, o11);
            } else {
                *(float2*)&C[(size_t)r * DIM + col]       = make_float2(o00, o01);
                *(float2*)&C[(size_t)(r + 8) * DIM + col] = make_float2(o10, o11);
            }
        }
    }
}

// ---------------- flash attention, fp16 mma (R8 exact) ------------------------
#define AQSH 72
#define QH    (128 * AQSH)                 // 9216 halves
#define KVSTH (64 * AQSH * 2)              // K+V stage halves
#define OFFK(b) (QH + (b) * KVSTH)
#define OFFV(b) (QH + (b) * KVSTH + 64 * AQSH)
#define ASMEM ((QH + 2 * KVSTH) * 2)       // 55296 bytes
#define NT    (SEQ / 64)
#define SCL   0.18033688011112042f         // 0.125 * log2(e)

__global__ __launch_bounds__(256) void k_attn_h()
{
    extern __shared__ __half smh[];
    const uint32_t smb = smem_u32(smh);

    const int tid  = threadIdx.x;
    const int lane = tid & 31;
    const int wid  = tid >> 5;
    const int j    = lane & 3;
    const int qt = blockIdx.x, h = blockIdx.y, b = blockIdx.z;
    const size_t qbase  = (size_t)(b * SEQ + qt * 128);
    const size_t kvbase = (size_t)(b * SEQ) * DIM + h * 64;

    auto copy_q = [&]() {
        #pragma unroll
        for (int i = 0; i < 4; i++) {
            int idx = i * 256 + tid;
            int r = idx >> 3, c8 = idx & 7;
            cp16(smb + (r * AQSH + c8 * 8) * 2,
                 g_qh + (qbase + r) * DIM + h * 64 + c8 * 8);
        }
    };
    auto copy_kv = [&](int buf, int kt) {
        uint32_t kb = smb + OFFK(buf) * 2;
        uint32_t vb = smb + OFFV(buf) * 2;
        #pragma unroll
        for (int i = 0; i < 2; i++) {
            int idx = i * 256 + tid;
            int r = idx >> 3, c8 = idx & 7;
            size_t g = kvbase + (size_t)(kt * 64 + r) * DIM + c8 * 8;
            cp16(kb + (r * AQSH + c8 * 8) * 2, g_kh + g);
            cp16(vb + (r * AQSH + c8 * 8) * 2, g_vh + g);
        }
    };

    float Oa[8][4];
    #pragma unroll
    for (int nt = 0; nt < 8; nt++)
        #pragma unroll
        for (int q = 0; q < 4; q++) Oa[nt][q] = 0.f;
    float m0 = -1e30f, m1 = -1e30f, l0 = 0.f, l1 = 0.f;  // log2 domain

    copy_q(); copy_kv(0, 0); CP_COMMIT();
    CP_WAIT0(); __syncthreads();

    for (int kt = 0; kt < NT; kt++) {
        int bu = kt & 1;
        if (kt + 1 < NT) { copy_kv(bu ^ 1, kt + 1); CP_COMMIT(); }

        const __half* Qs = smh;
        const __half* Ks = smh + OFFK(bu);
        const __half* Vs = smh + OFFV(bu);

        // ---- S = Q @ K^T ----
        float Sa[8][4];
        #pragma unroll
        for (int nt = 0; nt < 8; nt++)
            #pragma unroll
            for (int q = 0; q < 4; q++) Sa[nt][q] = 0.f;
        #pragma unroll
        for (int kk = 0; kk < 64; kk += 16) {
            uint32_t af[4];
            int r = wid * 16 + (lane >> 2);
            int c = kk + 2 * j;
            af[0] = *(const uint32_t*)&Qs[r * AQSH + c];
            af[1] = *(const uint32_t*)&Qs[(r + 8) * AQSH + c];
            af[2] = *(const uint32_t*)&Qs[r * AQSH + c + 8];
            af[3] = *(const uint32_t*)&Qs[(r + 8) * AQSH + c + 8];
            #pragma unroll
            for (int nt = 0; nt < 8; nt++) {
                int n = nt * 8 + (lane >> 2);
                uint32_t bf[2];
                bf[0] = *(const uint32_t*)&Ks[n * AQSH + c];
                bf[1] = *(const uint32_t*)&Ks[n * AQSH + c + 8];
                mma_f16(Sa[nt], af, bf);
            }
        }

        // ---- online softmax (exp2 domain) ----
        #pragma unroll
        for (int nt = 0; nt < 8; nt++)
            #pragma unroll
            for (int q = 0; q < 4; q++) Sa[nt][q] *= SCL;

        float mx0 = m0, mx1 = m1;
        #pragma unroll
        for (int nt = 0; nt < 8; nt++) {
            mx0 = fmaxf(mx0, fmaxf(Sa[nt][0], Sa[nt][1]));
            mx1 = fmaxf(mx1, fmaxf(Sa[nt][2], Sa[nt][3]));
        }
        #pragma unroll
        for (int o = 1; o <= 2; o <<= 1) {
            mx0 = fmaxf(mx0, __shfl_xor_sync(0xffffffffu, mx0, o));
            mx1 = fmaxf(mx1, __shfl_xor_sync(0xffffffffu, mx1, o));
        }
        float corr0 = exp2f(m0 - mx0);
        float corr1 = exp2f(m1 - mx1);
        m0 = mx0; m1 = mx1;

        float s0 = 0.f, s1 = 0.f;
        #pragma unroll
        for (int nt = 0; nt < 8; nt++) {
            Sa[nt][0] = exp2f(Sa[nt][0] - m0);
            Sa[nt][1] = exp2f(Sa[nt][1] - m0);
            Sa[nt][2] = exp2f(Sa[nt][2] - m1);
            Sa[nt][3] = exp2f(Sa[nt][3] - m1);
            s0 += Sa[nt][0] + Sa[nt][1];
            s1 += Sa[nt][2] + Sa[nt][3];
        }
        #pragma unroll
        for (int o = 1; o <= 2; o <<= 1) {
            s0 += __shfl_xor_sync(0xffffffffu, s0, o);
            s1 += __shfl_xor_sync(0xffffffffu, s1, o);
        }
        l0 = l0 * corr0 + s0;
        l1 = l1 * corr1 + s1;
        #pragma unroll
        for (int nt = 0; nt < 8; nt++) {
            Oa[nt][0] *= corr0; Oa[nt][1] *= corr0;
            Oa[nt][2] *= corr1; Oa[nt][3] *= corr1;
        }

        // ---- O += P @ V  (A-frags = local packs of Sa) ----
        #pragma unroll
        for (int kk2 = 0; kk2 < 4; kk2++) {
            uint32_t af[4];
            af[0] = packf(Sa[2 * kk2][0],     Sa[2 * kk2][1]);
            af[1] = packf(Sa[2 * kk2][2],     Sa[2 * kk2][3]);
            af[2] = packf(Sa[2 * kk2 + 1][0], Sa[2 * kk2 + 1][1]);
            af[3] = packf(Sa[2 * kk2 + 1][2], Sa[2 * kk2 + 1][3]);
            int krow = kk2 * 16 + 2 * j;
            #pragma unroll
            for (int nt = 0; nt < 8; nt++) {
                int n = nt * 8 + (lane >> 2);
                uint32_t bf[2];
                bf[0] = packh(Vs[krow * AQSH + n],       Vs[(krow + 1) * AQSH + n]);
                bf[1] = packh(Vs[(krow + 8) * AQSH + n], Vs[(krow + 9) * AQSH + n]);
                mma_f16(Oa[nt], af, bf);
            }
        }

        CP_WAIT0(); __syncthreads();
    }

    float inv0 = 1.f / l0, inv1 = 1.f / l1;
    size_t r = qbase + wid * 16 + (lane >> 2);
    #pragma unroll
    for (int nt = 0; nt < 8; nt++) {
        int col = h * 64 + nt * 8 + 2 * j;
        *(uint32_t*)&g_ah[r * DIM + col] =
            packf(Oa[nt][0] * inv0, Oa[nt][1] * inv0);
        *(uint32_t*)&g_ah[(r + 8) * DIM + col] =
            packf(Oa[nt][2] * inv1, Oa[nt][3] * inv1);
    }
}

// ---------------- residual + layernorm ---------------------------------------
__global__ __launch_bounds__(256) void k_ln(const float* __restrict__ gamma,
                                            const float* __restrict__ beta,
                                            float* __restrict__ out)
{
    __shared__ float ws[8], wss[8];
    const int row = blockIdx.x;
    const int tid = threadIdx.x;

    const float4* p4 = (const float4*)(g_proj + (size_t)row * DIM);
    const float4* x4 = (const float4*)(g_xpe  + (size_t)row * DIM);
    float4 a = p4[tid];
    float4 b = x4[tid];
    float4 hv = make_float4(a.x + b.x, a.y + b.y, a.z + b.z, a.w + b.w);

    float s  = hv.x + hv.y + hv.z + hv.w;
    float ss = hv.x * hv.x + hv.y * hv.y + hv.z * hv.z + hv.w * hv.w;
    #pragma unroll
    for (int o = 16; o; o >>= 1) {
        s  += __shfl_xor_sync(0xffffffffu, s,  o);
        ss += __shfl_xor_sync(0xffffffffu, ss, o);
    }
    int w = tid >> 5;
    if ((tid & 31) == 0) { ws[w] = s; wss[w] = ss; }
    __syncthreads();

    float ts = 0.f, tss = 0.f;
    #pragma unroll
    for (int i = 0; i < 8; i++) { ts += ws[i]; tss += wss[i]; }
    float mean = ts * (1.f / 1024.f);
    float var  = tss * (1.f / 1024.f) - mean * mean;
    float rstd = rsqrtf(var + 1e-5f);

    float4 g  = ((const float4*)gamma)[tid];
    float4 be = ((const float4*)beta)[tid];
    float4 o;
    o.x = (hv.x - mean) * rstd * g.x + be.x;
    o.y = (hv.y - mean) * rstd * g.y + be.y;
    o.z = (hv.z - mean) * rstd * g.z + be.z;
    o.w = (hv.w - mean) * rstd * g.w + be.w;
    ((float4*)out)[(size_t)row * 256 + tid] = o;
}

// ---------------- launch ------------------------------------------------------
extern "C" void kernel_launch(void* const* d_in, const int* in_sizes, int n_in,
                              void* d_out, int out_size)
{
    const float* x     = (const float*)d_in[0];
    const float* wq    = (const float*)d_in[1];
    const float* bq    = (const float*)d_in[2];
    const float* wk    = (const float*)d_in[3];
    const float* bk    = (const float*)d_in[4];
    const float* wv    = (const float*)d_in[5];
    const float* bv    = (const float*)d_in[6];
    const float* wo    = (const float*)d_in[7];
    const float* bo    = (const float*)d_in[8];
    const float* gamma = (const float*)d_in[9];
    const float* beta  = (const float*)d_in[10];
    const float* pe    = (const float*)d_in[11];
    float* out = (float*)d_out;

    void *pxh, *pqh, *pkh, *pvh, *pah, *pproj, *pwTh;
    cudaGetSymbolAddress(&pxh,   g_xh);
    cudaGetSymbolAddress(&pqh,   g_qh);
    cudaGetSymbolAddress(&pkh,   g_kh);
    cudaGetSymbolAddress(&pvh,   g_vh);
    cudaGetSymbolAddress(&pah,   g_ah);
    cudaGetSymbolAddress(&pproj, g_proj);
    cudaGetSymbolAddress(&pwTh,  g_wTh);
    __half* wTh = (__half*)pwTh;

    cudaFuncSetAttribute(k_gemm_h<__half>, cudaFuncAttributeMaxDynamicSharedMemorySize, GSMEM);
    cudaFuncSetAttribute(k_gemm_h<float>,  cudaFuncAttributeMaxDynamicSharedMemorySize, GSMEM);
    cudaFuncSetAttribute(k_attn_h, cudaFuncAttributeMaxDynamicSharedMemorySize, ASMEM);

    k_addpe<<<(NTOK * DIM / 4) / 256, 256>>>(x, pe);

    dim3 tgrid(DIM / 32, DIM / 32, 4);
    k_transpose4<<<tgrid, 256>>>(wq, wk, wv, wo);

    // fused QKV: grid.z = 3 selects weight/bias/output
    dim3 qkvgrid(DIM / 128, NTOK / 128, 3);      // (8, 64, 3)
    k_gemm_h<__half><<<qkvgrid, 256, GSMEM>>>(
        (const __half*)pxh,
        wTh + 0 * DIM * DIM, wTh + 1 * DIM * DIM, wTh + 2 * DIM * DIM,
        bq, bk, bv,
        (__half*)pqh, (__half*)pkh, (__half*)pvh);

    dim3 agrid(SEQ / 128, NH, BATCH);            // (16, 16, 4)
    k_attn_h<<<agrid, 256, ASMEM>>>();

    dim3 ogrid(DIM / 128, NTOK / 128, 1);
    k_gemm_h<float><<<ogrid, 256, GSMEM>>>(
        (const __half*)pah,
        wTh + 3 * DIM * DIM, wTh + 3 * DIM * DIM, wTh + 3 * DIM * DIM,
        bo, bo, bo,
        (float*)pproj, (float*)pproj, (float*)pproj);

    k_ln<<<NTOK, 256>>>(gamma, beta, out);
}

// round 11
// speedup vs baseline: 1.2567x; 1.0831x over previous
#include <cuda_runtime.h>
#include <cuda_fp16.h>
#include <cstdint>

#define SEQ   2048
#define BATCH 4
#define NTOK  (SEQ * BATCH)      // 8192
#define DIM   1024
#define NH    16
#define HD    64

// ---------------- scratch (device globals per allocation rules) -------------
__device__ float  g_xpe [NTOK * DIM];     // fp32 residual for LN
__device__ float  g_proj[NTOK * DIM];     // fp32 O-projection for LN
__device__ __half g_xh  [NTOK * DIM];     // half x+pe (GEMM A)
__device__ __half g_qh  [NTOK * DIM];
__device__ __half g_kh  [NTOK * DIM];
__device__ __half g_vh  [NTOK * DIM];
__device__ __half g_ah  [NTOK * DIM];     // attention output (half)
__device__ __half g_wTh [4][DIM * DIM];   // transposed weights [N][K], half

// ---------------- helpers -----------------------------------------------------
__device__ __forceinline__ uint32_t smem_u32(const void* p) {
    uint32_t a;
    asm("{ .reg .u64 t; cvta.to.shared.u64 t, %1; cvt.u32.u64 %0, t; }" : "=r"(a) : "l"(p));
    return a;
}
__device__ __forceinline__ void cp16(uint32_t dst, const void* src) {
    asm volatile("cp.async.cg.shared.global [%0], [%1], 16;" :: "r"(dst), "l"(src));
}
#define CP_COMMIT() asm volatile("cp.async.commit_group;" ::: "memory")
#define CP_WAIT0()  asm volatile("cp.async.wait_group 0;" ::: "memory")
#define CP_WAIT1()  asm volatile("cp.async.wait_group 1;" ::: "memory")

__device__ __forceinline__ void mma_f16(float* d, const uint32_t* a, const uint32_t* b) {
    asm volatile(
        "mma.sync.aligned.m16n8k16.row.col.f32.f16.f16.f32 "
        "{%0,%1,%2,%3}, {%4,%5,%6,%7}, {%8,%9}, {%0,%1,%2,%3};\n"
        : "+f"(d[0]), "+f"(d[1]), "+f"(d[2]), "+f"(d[3])
        : "r"(a[0]), "r"(a[1]), "r"(a[2]), "r"(a[3]), "r"(b[0]), "r"(b[1]));
}
__device__ __forceinline__ void ldsm4(uint32_t* r, uint32_t addr) {
    asm volatile("ldmatrix.sync.aligned.m8n8.x4.shared.b16 {%0,%1,%2,%3}, [%4];"
        : "=r"(r[0]), "=r"(r[1]), "=r"(r[2]), "=r"(r[3]) : "r"(addr));
}
__device__ __forceinline__ void ldsm4t(uint32_t* r, uint32_t addr) {
    asm volatile("ldmatrix.sync.aligned.m8n8.x4.trans.shared.b16 {%0,%1,%2,%3}, [%4];"
        : "=r"(r[0]), "=r"(r[1]), "=r"(r[2]), "=r"(r[3]) : "r"(addr));
}
__device__ __forceinline__ uint32_t packf(float x, float y) {
    __half2 t = __floats2half2_rn(x, y);
    return *(uint32_t*)&t;
}

// ---------------- x + pe (fp32 out + half out) -------------------------------
__global__ void k_addpe(const float* __restrict__ x, const float* __restrict__ pe) {
    int idx = blockIdx.x * 256 + threadIdx.x;        // float4 index
    const float4* x4  = (const float4*)x;
    const float4* pe4 = (const float4*)pe;
    float4*       o4  = (float4*)g_xpe;
    int row = idx >> 8;
    int c   = idx & 255;
    int s   = row & (SEQ - 1);
    float4 a = x4[idx];
    float4 b = pe4[s * 256 + c];
    a.x += b.x; a.y += b.y; a.z += b.z; a.w += b.w;
    o4[idx] = a;
    uint2 hp;
    hp.x = packf(a.x, a.y);
    hp.y = packf(a.z, a.w);
    *(uint2*)&g_xh[(size_t)idx * 4] = hp;
}

// ---------------- fused weight transpose -> half ------------------------------
__global__ __launch_bounds__(256) void k_transpose4(
    const float* __restrict__ w0, const float* __restrict__ w1,
    const float* __restrict__ w2, const float* __restrict__ w3)
{
    __shared__ float t[32][33];
    const float* in;
    switch (blockIdx.z) {
        case 0: in = w0; break;
        case 1: in = w1; break;
        case 2: in = w2; break;
        default: in = w3; break;
    }
    __half* out = g_wTh[blockIdx.z];
    int n0 = blockIdx.x * 32, k0 = blockIdx.y * 32;
    int tx = threadIdx.x & 31, ty = threadIdx.x >> 5;
    #pragma unroll
    for (int i = ty; i < 32; i += 8)
        t[i][tx] = in[(size_t)(k0 + i) * DIM + n0 + tx];
    __syncthreads();
    #pragma unroll
    for (int i = ty; i < 32; i += 8)
        out[(size_t)(n0 + i) * DIM + k0 + tx] = __float2half(t[tx][i]);
}

// ---------------- fp16 mma GEMM: C[M,N] = A[M,K] @ Bt[N,K]^T + bias ----------
// 128x128 CTA tile, BK=64 halves, 8 warps (4x2), padded smem, 3-stage pipeline,
// ldmatrix fragment loads. blockIdx.z selects weight/bias/output (QKV fusion).
#define GPADH 72
#define TILEH (128 * GPADH)                 // halves per operand tile
#define STAGEB (2 * TILEH * 2)              // bytes per stage (A+B) = 36864
#define GSMEM (3 * STAGEB)                  // 110592 bytes
#define NCH   (DIM / 64)                    // 16 stages

template <typename OutT>
__global__ __launch_bounds__(256) void k_gemm_h(
    const __half* __restrict__ A,
    const __half* __restrict__ Bt0, const __half* __restrict__ Bt1, const __half* __restrict__ Bt2,
    const float* __restrict__ bi0,  const float* __restrict__ bi1,  const float* __restrict__ bi2,
    OutT* __restrict__ C0, OutT* __restrict__ C1, OutT* __restrict__ C2)
{
    extern __shared__ __half smh[];
    const uint32_t smb = smem_u32(smh);
    const int tid  = threadIdx.x;
    const int lane = tid & 31;
    const int wid  = tid >> 5;
    const int wr   = wid & 3;
    const int wc   = wid >> 2;
    const int j    = lane & 3;
    const int rowBase = blockIdx.y * 128;
    const int colBase = blockIdx.x * 128;

    const __half* Bt   = (blockIdx.z == 0) ? Bt0 : (blockIdx.z == 1) ? Bt1 : Bt2;
    const float*  bias = (blockIdx.z == 0) ? bi0 : (blockIdx.z == 1) ? bi1 : bi2;
    OutT*         C    = (blockIdx.z == 0) ? C0  : (blockIdx.z == 1) ? C1  : C2;

    const __half* Ab = A  + (size_t)rowBase * DIM;
    const __half* Bb = Bt + (size_t)colBase * DIM;

    // ldmatrix lane geometry (shared by A and B tiles)
    const int lrow = lane & 15;              // row within 16-row block
    const int lcol = (lane >> 4) << 3;       // 0 or 8 (k column block)

    float acc[2][8][4];
    #pragma unroll
    for (int mt = 0; mt < 2; mt++)
        #pragma unroll
        for (int nt = 0; nt < 8; nt++)
            #pragma unroll
            for (int q = 0; q < 4; q++) acc[mt][nt][q] = 0.f;

    auto copy_tile = [&](int buf, int chunk) {
        uint32_t as_ = smb + buf * STAGEB;
        uint32_t bs_ = as_ + TILEH * 2;
        #pragma unroll
        for (int i = 0; i < 4; i++) {
            int idx = i * 256 + tid;        // 0..1023
            int r = idx >> 3, c8 = idx & 7; // row, 8-half chunk
            uint32_t off = (r * GPADH + c8 * 8) * 2;
            cp16(as_ + off, Ab + (size_t)r * DIM + chunk * 64 + c8 * 8);
            cp16(bs_ + off, Bb + (size_t)r * DIM + chunk * 64 + c8 * 8);
        }
    };
    auto compute = [&](int buf) {
        const uint32_t as_ = smb + buf * STAGEB;
        const uint32_t bs_ = as_ + TILEH * 2;
        #pragma unroll
        for (int kk = 0; kk < 64; kk += 16) {
            uint32_t af[2][4];
            int arow = wr * 32 + lrow;
            int acol = kk + lcol;
            ldsm4(af[0], as_ + (uint32_t)(arow * GPADH + acol) * 2);
            ldsm4(af[1], as_ + (uint32_t)((arow + 16) * GPADH + acol) * 2);
            #pragma unroll
            for (int p = 0; p < 4; p++) {
                uint32_t bm[4];
                int brow = wc * 64 + p * 16 + lrow;
                ldsm4(bm, bs_ + (uint32_t)(brow * GPADH + acol) * 2);
                uint32_t bf0[2] = { bm[0], bm[2] };
                uint32_t bf1[2] = { bm[1], bm[3] };
                mma_f16(acc[0][2 * p],     af[0], bf0);
                mma_f16(acc[1][2 * p],     af[1], bf0);
                mma_f16(acc[0][2 * p + 1], af[0], bf1);
                mma_f16(acc[1][2 * p + 1], af[1], bf1);
            }
        }
    };

    // 3-stage pipeline; always commit one group per iteration (possibly empty)
    copy_tile(0, 0); CP_COMMIT();
    copy_tile(1, 1); CP_COMMIT();
    int buf = 0;
    for (int c = 0; c < NCH; c++) {
        CP_WAIT1();                         // oldest group (stage c) done
        __syncthreads();
        if (c + 2 < NCH) copy_tile((buf + 2) % 3, c + 2);
        CP_COMMIT();
        compute(buf);
        buf = (buf + 1) % 3;
    }

    #pragma unroll
    for (int mt = 0; mt < 2; mt++) {
        int r = rowBase + wr * 32 + mt * 16 + (lane >> 2);
        #pragma unroll
        for (int nt = 0; nt < 8; nt++) {
            int col = colBase + wc * 64 + nt * 8 + 2 * j;
            float2 b2 = *(const float2*)&bias[col];
            float o00 = acc[mt][nt][0] + b2.x, o01 = acc[mt][nt][1] + b2.y;
            float o10 = acc[mt][nt][2] + b2.x, o11 = acc[mt][nt][3] + b2.y;
            if constexpr (sizeof(OutT) == 2) {
                *(uint32_t*)&C[(size_t)r * DIM + col]       = packf(o00, o01);
                *(uint32_t*)&C[(size_t)(r + 8) * DIM + col] = packf(o10, o11);
            } else {
                *(float2*)&C[(size_t)r * DIM + col]       = make_float2(o00, o01);
                *(float2*)&C[(size_t)(r + 8) * DIM + col] = make_float2(o10, o11);
            }
        }
    }
}

// ---------------- flash attention, fp16 mma + ldmatrix ------------------------
#define AQSH 72
#define QH    (128 * AQSH)                 // 9216 halves
#define KVSTH (64 * AQSH * 2)              // K+V stage halves
#define OFFK(b) (QH + (b) * KVSTH)
#define OFFV(b) (QH + (b) * KVSTH + 64 * AQSH)
#define ASMEM ((QH + 2 * KVSTH) * 2)       // 55296 bytes
#define NT    (SEQ / 64)
#define SCL   0.18033688011112042f         // 0.125 * log2(e)

__global__ __launch_bounds__(256) void k_attn_h()
{
    extern __shared__ __half smh[];
    const uint32_t smb = smem_u32(smh);

    const int tid  = threadIdx.x;
    const int lane = tid & 31;
    const int wid  = tid >> 5;
    const int qt = blockIdx.x, h = blockIdx.y, b = blockIdx.z;
    const size_t qbase  = (size_t)(b * SEQ + qt * 128);
    const size_t kvbase = (size_t)(b * SEQ) * DIM + h * 64;

    const int lrow = lane & 15;
    const int lcol = (lane >> 4) << 3;
    const int vrow = ((lane >> 4) << 3) + (lane & 7);  // k-row within 16 block
    const int vcol = lane & 8;                          // n sub-block 0/8

    auto copy_q = [&]() {
        #pragma unroll
        for (int i = 0; i < 4; i++) {
            int idx = i * 256 + tid;
            int r = idx >> 3, c8 = idx & 7;
            cp16(smb + (r * AQSH + c8 * 8) * 2,
                 g_qh + (qbase + r) * DIM + h * 64 + c8 * 8);
        }
    };
    auto copy_kv = [&](int buf, int kt) {
        uint32_t kb = smb + OFFK(buf) * 2;
        uint32_t vb = smb + OFFV(buf) * 2;
        #pragma unroll
        for (int i = 0; i < 2; i++) {
            int idx = i * 256 + tid;
            int r = idx >> 3, c8 = idx & 7;
            size_t g = kvbase + (size_t)(kt * 64 + r) * DIM + c8 * 8;
            cp16(kb + (r * AQSH + c8 * 8) * 2, g_kh + g);
            cp16(vb + (r * AQSH + c8 * 8) * 2, g_vh + g);
        }
    };

    float Oa[8][4];
    #pragma unroll
    for (int nt = 0; nt < 8; nt++)
        #pragma unroll
        for (int q = 0; q < 4; q++) Oa[nt][q] = 0.f;
    float m0 = -1e30f, m1 = -1e30f, l0 = 0.f, l1 = 0.f;  // log2 domain

    copy_q(); copy_kv(0, 0); CP_COMMIT();
    CP_WAIT0(); __syncthreads();

    for (int kt = 0; kt < NT; kt++) {
        int bu = kt & 1;
        if (kt + 1 < NT) { copy_kv(bu ^ 1, kt + 1); CP_COMMIT(); }

        const uint32_t qb = smb;
        const uint32_t kb = smb + OFFK(bu) * 2;
        const uint32_t vb = smb + OFFV(bu) * 2;

        // ---- S = Q @ K^T ----
        float Sa[8][4];
        #pragma unroll
        for (int nt = 0; nt < 8; nt++)
            #pragma unroll
            for (int q = 0; q < 4; q++) Sa[nt][q] = 0.f;
        #pragma unroll
        for (int kk = 0; kk < 64; kk += 16) {
            uint32_t af[4];
            int arow = wid * 16 + lrow;
            int acol = kk + lcol;
            ldsm4(af, qb + (uint32_t)(arow * AQSH + acol) * 2);
            #pragma unroll
            for (int p = 0; p < 4; p++) {
                uint32_t bm[4];
                int brow = p * 16 + lrow;
                ldsm4(bm, kb + (uint32_t)(brow * AQSH + acol) * 2);
                uint32_t bf0[2] = { bm[0], bm[2] };
                uint32_t bf1[2] = { bm[1], bm[3] };
                mma_f16(Sa[2 * p],     af, bf0);
                mma_f16(Sa[2 * p + 1], af, bf1);
            }
        }

        // ---- online softmax (exp2 domain) ----
        #pragma unroll
        for (int nt = 0; nt < 8; nt++)
            #pragma unroll
            for (int q = 0; q < 4; q++) Sa[nt][q] *= SCL;

        float mx0 = m0, mx1 = m1;
        #pragma unroll
        for (int nt = 0; nt < 8; nt++) {
            mx0 = fmaxf(mx0, fmaxf(Sa[nt][0], Sa[nt][1]));
            mx1 = fmaxf(mx1, fmaxf(Sa[nt][2], Sa[nt][3]));
        }
        #pragma unroll
        for (int o = 1; o <= 2; o <<= 1) {
            mx0 = fmaxf(mx0, __shfl_xor_sync(0xffffffffu, mx0, o));
            mx1 = fmaxf(mx1, __shfl_xor_sync(0xffffffffu, mx1, o));
        }
        float corr0 = exp2f(m0 - mx0);
        float corr1 = exp2f(m1 - mx1);
        m0 = mx0; m1 = mx1;

        float s0 = 0.f, s1 = 0.f;
        #pragma unroll
        for (int nt = 0; nt < 8; nt++) {
            Sa[nt][0] = exp2f(Sa[nt][0] - m0);
            Sa[nt][1] = exp2f(Sa[nt][1] - m0);
            Sa[nt][2] = exp2f(Sa[nt][2] - m1);
            Sa[nt][3] = exp2f(Sa[nt][3] - m1);
            s0 += Sa[nt][0] + Sa[nt][1];
            s1 += Sa[nt][2] + Sa[nt][3];
        }
        #pragma unroll
        for (int o = 1; o <= 2; o <<= 1) {
            s0 += __shfl_xor_sync(0xffffffffu, s0, o);
            s1 += __shfl_xor_sync(0xffffffffu, s1, o);
        }
        l0 = l0 * corr0 + s0;
        l1 = l1 * corr1 + s1;
        #pragma unroll
        for (int nt = 0; nt < 8; nt++) {
            Oa[nt][0] *= corr0; Oa[nt][1] *= corr0;
            Oa[nt][2] *= corr1; Oa[nt][3] *= corr1;
        }

        // ---- O += P @ V  (A = local packs of Sa; B via ldmatrix.trans) ----
        #pragma unroll
        for (int kk2 = 0; kk2 < 4; kk2++) {
            uint32_t af[4];
            af[0] = packf(Sa[2 * kk2][0],     Sa[2 * kk2][1]);
            af[1] = packf(Sa[2 * kk2][2],     Sa[2 * kk2][3]);
            af[2] = packf(Sa[2 * kk2 + 1][0], Sa[2 * kk2 + 1][1]);
            af[3] = packf(Sa[2 * kk2 + 1][2], Sa[2 * kk2 + 1][3]);
            int vr = kk2 * 16 + vrow;
            #pragma unroll
            for (int p = 0; p < 4; p++) {
                uint32_t vm[4];
                int vc = p * 16 + vcol;
                ldsm4t(vm, vb + (uint32_t)(vr * AQSH + vc) * 2);
                uint32_t bf0[2] = { vm[0], vm[2] };
                uint32_t bf1[2] = { vm[1], vm[3] };
                mma_f16(Oa[2 * p],     af, bf0);
                mma_f16(Oa[2 * p + 1], af, bf1);
            }
        }

        CP_WAIT0(); __syncthreads();
    }

    float inv0 = 1.f / l0, inv1 = 1.f / l1;
    size_t r = qbase + wid * 16 + (lane >> 2);
    #pragma unroll
    for (int nt = 0; nt < 8; nt++) {
        int col = h * 64 + nt * 8 + 2 * (lane & 3);
        *(uint32_t*)&g_ah[r * DIM + col] =
            packf(Oa[nt][0] * inv0, Oa[nt][1] * inv0);
        *(uint32_t*)&g_ah[(r + 8) * DIM + col] =
            packf(Oa[nt][2] * inv1, Oa[nt][3] * inv1);
    }
}

// ---------------- residual + layernorm ---------------------------------------
__global__ __launch_bounds__(256) void k_ln(const float* __restrict__ gamma,
                                            const float* __restrict__ beta,
                                            float* __restrict__ out)
{
    __shared__ float ws[8], wss[8];
    const int row = blockIdx.x;
    const int tid = threadIdx.x;

    const float4* p4 = (const float4*)(g_proj + (size_t)row * DIM);
    const float4* x4 = (const float4*)(g_xpe  + (size_t)row * DIM);
    float4 a = p4[tid];
    float4 b = x4[tid];
    float4 hv = make_float4(a.x + b.x, a.y + b.y, a.z + b.z, a.w + b.w);

    float s  = hv.x + hv.y + hv.z + hv.w;
    float ss = hv.x * hv.x + hv.y * hv.y + hv.z * hv.z + hv.w * hv.w;
    #pragma unroll
    for (int o = 16; o; o >>= 1) {
        s  += __shfl_xor_sync(0xffffffffu, s,  o);
        ss += __shfl_xor_sync(0xffffffffu, ss, o);
    }
    int w = tid >> 5;
    if ((tid & 31) == 0) { ws[w] = s; wss[w] = ss; }
    __syncthreads();

    float ts = 0.f, tss = 0.f;
    #pragma unroll
    for (int i = 0; i < 8; i++) { ts += ws[i]; tss += wss[i]; }
    float mean = ts * (1.f / 1024.f);
    float var  = tss * (1.f / 1024.f) - mean * mean;
    float rstd = rsqrtf(var + 1e-5f);

    float4 g  = ((const float4*)gamma)[tid];
    float4 be = ((const float4*)beta)[tid];
    float4 o;
    o.x = (hv.x - mean) * rstd * g.x + be.x;
    o.y = (hv.y - mean) * rstd * g.y + be.y;
    o.z = (hv.z - mean) * rstd * g.z + be.z;
    o.w = (hv.w - mean) * rstd * g.w + be.w;
    ((float4*)out)[(size_t)row * 256 + tid] = o;
}

// ---------------- launch ------------------------------------------------------
extern "C" void kernel_launch(void* const* d_in, const int* in_sizes, int n_in,
                              void* d_out, int out_size)
{
    const float* x     = (const float*)d_in[0];
    const float* wq    = (const float*)d_in[1];
    const float* bq    = (const float*)d_in[2];
    const float* wk    = (const float*)d_in[3];
    const float* bk    = (const float*)d_in[4];
    const float* wv    = (const float*)d_in[5];
    const float* bv    = (const float*)d_in[6];
    const float* wo    = (const float*)d_in[7];
    const float* bo    = (const float*)d_in[8];
    const float* gamma = (const float*)d_in[9];
    const float* beta  = (const float*)d_in[10];
    const float* pe    = (const float*)d_in[11];
    float* out = (float*)d_out;

    void *pxh, *pqh, *pkh, *pvh, *pah, *pproj, *pwTh;
    cudaGetSymbolAddress(&pxh,   g_xh);
    cudaGetSymbolAddress(&pqh,   g_qh);
    cudaGetSymbolAddress(&pkh,   g_kh);
    cudaGetSymbolAddress(&pvh,   g_vh);
    cudaGetSymbolAddress(&pah,   g_ah);
    cudaGetSymbolAddress(&pproj, g_proj);
    cudaGetSymbolAddress(&pwTh,  g_wTh);
    __half* wTh = (__half*)pwTh;

    cudaFuncSetAttribute(k_gemm_h<__half>, cudaFuncAttributeMaxDynamicSharedMemorySize, GSMEM);
    cudaFuncSetAttribute(k_gemm_h<float>,  cudaFuncAttributeMaxDynamicSharedMemorySize, GSMEM);
    cudaFuncSetAttribute(k_attn_h, cudaFuncAttributeMaxDynamicSharedMemorySize, ASMEM);

    k_addpe<<<(NTOK * DIM / 4) / 256, 256>>>(x, pe);

    dim3 tgrid(DIM / 32, DIM / 32, 4);
    k_transpose4<<<tgrid, 256>>>(wq, wk, wv, wo);

    // fused QKV: grid.z = 3 selects weight/bias/output
    dim3 qkvgrid(DIM / 128, NTOK / 128, 3);      // (8, 64, 3)
    k_gemm_h<__half><<<qkvgrid, 256, GSMEM>>>(
        (const __half*)pxh,
        wTh + 0 * DIM * DIM, wTh + 1 * DIM * DIM, wTh + 2 * DIM * DIM,
        bq, bk, bv,
        (__half*)pqh, (__half*)pkh, (__half*)pvh);

    dim3 agrid(SEQ / 128, NH, BATCH);            // (16, 16, 4)
    k_attn_h<<<agrid, 256, ASMEM>>>();

    dim3 ogrid(DIM / 128, NTOK / 128, 1);
    k_gemm_h<float><<<ogrid, 256, GSMEM>>>(
        (const __half*)pah,
        wTh + 3 * DIM * DIM, wTh + 3 * DIM * DIM, wTh + 3 * DIM * DIM,
        bo, bo, bo,
        (float*)pproj, (float*)pproj, (float*)pproj);

    k_ln<<<NTOK, 256>>>(gamma, beta, out);
}

// round 12
// speedup vs baseline: 1.2781x; 1.0170x over previous
#include <cuda_runtime.h>
#include <cuda_fp16.h>
#include <cstdint>

#define SEQ   2048
#define BATCH 4
#define NTOK  (SEQ * BATCH)      // 8192
#define DIM   1024
#define NH    16
#define HD    64

// ---------------- scratch (device globals per allocation rules) -------------
__device__ float  g_xpe [NTOK * DIM];     // fp32 residual for LN
__device__ float  g_proj[NTOK * DIM];     // fp32 O-projection for LN
__device__ __half g_xh  [NTOK * DIM];     // half x+pe (GEMM A)
__device__ __half g_qh  [NTOK * DIM];     // pre-scaled by 0.125*log2(e)
__device__ __half g_kh  [NTOK * DIM];
__device__ __half g_vh  [NTOK * DIM];
__device__ __half g_ah  [NTOK * DIM];     // attention output (half)
__device__ __half g_wTh [4][DIM * DIM];   // transposed weights [N][K], half

#define SCL 0.18033688011112042f          // 0.125 * log2(e)

// ---------------- helpers -----------------------------------------------------
__device__ __forceinline__ uint32_t smem_u32(const void* p) {
    uint32_t a;
    asm("{ .reg .u64 t; cvta.to.shared.u64 t, %1; cvt.u32.u64 %0, t; }" : "=r"(a) : "l"(p));
    return a;
}
__device__ __forceinline__ void cp16(uint32_t dst, const void* src) {
    asm volatile("cp.async.cg.shared.global [%0], [%1], 16;" :: "r"(dst), "l"(src));
}
#define CP_COMMIT() asm volatile("cp.async.commit_group;" ::: "memory")
#define CP_WAIT0()  asm volatile("cp.async.wait_group 0;" ::: "memory")
#define CP_WAIT1()  asm volatile("cp.async.wait_group 1;" ::: "memory")

__device__ __forceinline__ void mma_f16(float* d, const uint32_t* a, const uint32_t* b) {
    asm volatile(
        "mma.sync.aligned.m16n8k16.row.col.f32.f16.f16.f32 "
        "{%0,%1,%2,%3}, {%4,%5,%6,%7}, {%8,%9}, {%0,%1,%2,%3};\n"
        : "+f"(d[0]), "+f"(d[1]), "+f"(d[2]), "+f"(d[3])
        : "r"(a[0]), "r"(a[1]), "r"(a[2]), "r"(a[3]), "r"(b[0]), "r"(b[1]));
}
__device__ __forceinline__ void ldsm4(uint32_t* r, uint32_t addr) {
    asm volatile("ldmatrix.sync.aligned.m8n8.x4.shared.b16 {%0,%1,%2,%3}, [%4];"
        : "=r"(r[0]), "=r"(r[1]), "=r"(r[2]), "=r"(r[3]) : "r"(addr));
}
__device__ __forceinline__ void ldsm4t(uint32_t* r, uint32_t addr) {
    asm volatile("ldmatrix.sync.aligned.m8n8.x4.trans.shared.b16 {%0,%1,%2,%3}, [%4];"
        : "=r"(r[0]), "=r"(r[1]), "=r"(r[2]), "=r"(r[3]) : "r"(addr));
}
__device__ __forceinline__ uint32_t packf(float x, float y) {
    __half2 t = __floats2half2_rn(x, y);
    return *(uint32_t*)&t;
}

// ---------------- x + pe (fp32 out + half out) -------------------------------
__global__ void k_addpe(const float* __restrict__ x, const float* __restrict__ pe) {
    int idx = blockIdx.x * 256 + threadIdx.x;        // float4 index
    const float4* x4  = (const float4*)x;
    const float4* pe4 = (const float4*)pe;
    float4*       o4  = (float4*)g_xpe;
    int row = idx >> 8;
    int c   = idx & 255;
    int s   = row & (SEQ - 1);
    float4 a = x4[idx];
    float4 b = pe4[s * 256 + c];
    a.x += b.x; a.y += b.y; a.z += b.z; a.w += b.w;
    o4[idx] = a;
    uint2 hp;
    hp.x = packf(a.x, a.y);
    hp.y = packf(a.z, a.w);
    *(uint2*)&g_xh[(size_t)idx * 4] = hp;
}

// ---------------- fused weight transpose -> half ------------------------------
__global__ __launch_bounds__(256) void k_transpose4(
    const float* __restrict__ w0, const float* __restrict__ w1,
    const float* __restrict__ w2, const float* __restrict__ w3)
{
    __shared__ float t[32][33];
    const float* in;
    switch (blockIdx.z) {
        case 0: in = w0; break;
        case 1: in = w1; break;
        case 2: in = w2; break;
        default: in = w3; break;
    }
    __half* out = g_wTh[blockIdx.z];
    int n0 = blockIdx.x * 32, k0 = blockIdx.y * 32;
    int tx = threadIdx.x & 31, ty = threadIdx.x >> 5;
    #pragma unroll
    for (int i = ty; i < 32; i += 8)
        t[i][tx] = in[(size_t)(k0 + i) * DIM + n0 + tx];
    __syncthreads();
    #pragma unroll
    for (int i = ty; i < 32; i += 8)
        out[(size_t)(n0 + i) * DIM + k0 + tx] = __float2half(t[tx][i]);
}

// ---------------- fp16 mma GEMM: C[M,N] = (A @ BtT + bias) * osc -------------
// osc applied only for blockIdx.z==0 (Q pre-scaling); 1.0 elsewhere.
#define GPADH 72
#define TILEH (128 * GPADH)                 // halves per operand tile
#define STAGEB (2 * TILEH * 2)              // bytes per stage (A+B) = 36864
#define GSMEM (3 * STAGEB)                  // 110592 bytes
#define NCH   (DIM / 64)                    // 16 stages

template <typename OutT>
__global__ __launch_bounds__(256) void k_gemm_h(
    const __half* __restrict__ A,
    const __half* __restrict__ Bt0, const __half* __restrict__ Bt1, const __half* __restrict__ Bt2,
    const float* __restrict__ bi0,  const float* __restrict__ bi1,  const float* __restrict__ bi2,
    OutT* __restrict__ C0, OutT* __restrict__ C1, OutT* __restrict__ C2,
    float qscale)
{
    extern __shared__ __half smh[];
    const uint32_t smb = smem_u32(smh);
    const int tid  = threadIdx.x;
    const int lane = tid & 31;
    const int wid  = tid >> 5;
    const int wr   = wid & 3;
    const int wc   = wid >> 2;
    const int j    = lane & 3;
    const int rowBase = blockIdx.y * 128;
    const int colBase = blockIdx.x * 128;

    const __half* Bt   = (blockIdx.z == 0) ? Bt0 : (blockIdx.z == 1) ? Bt1 : Bt2;
    const float*  bias = (blockIdx.z == 0) ? bi0 : (blockIdx.z == 1) ? bi1 : bi2;
    OutT*         C    = (blockIdx.z == 0) ? C0  : (blockIdx.z == 1) ? C1  : C2;
    const float   osc  = (blockIdx.z == 0) ? qscale : 1.f;

    const __half* Ab = A  + (size_t)rowBase * DIM;
    const __half* Bb = Bt + (size_t)colBase * DIM;

    const int lrow = lane & 15;
    const int lcol = (lane >> 4) << 3;

    float acc[2][8][4];
    #pragma unroll
    for (int mt = 0; mt < 2; mt++)
        #pragma unroll
        for (int nt = 0; nt < 8; nt++)
            #pragma unroll
            for (int q = 0; q < 4; q++) acc[mt][nt][q] = 0.f;

    auto copy_tile = [&](int buf, int chunk) {
        uint32_t as_ = smb + buf * STAGEB;
        uint32_t bs_ = as_ + TILEH * 2;
        #pragma unroll
        for (int i = 0; i < 4; i++) {
            int idx = i * 256 + tid;
            int r = idx >> 3, c8 = idx & 7;
            uint32_t off = (r * GPADH + c8 * 8) * 2;
            cp16(as_ + off, Ab + (size_t)r * DIM + chunk * 64 + c8 * 8);
            cp16(bs_ + off, Bb + (size_t)r * DIM + chunk * 64 + c8 * 8);
        }
    };
    auto compute = [&](int buf) {
        const uint32_t as_ = smb + buf * STAGEB;
        const uint32_t bs_ = as_ + TILEH * 2;
        #pragma unroll
        for (int kk = 0; kk < 64; kk += 16) {
            uint32_t af[2][4];
            int arow = wr * 32 + lrow;
            int acol = kk + lcol;
            ldsm4(af[0], as_ + (uint32_t)(arow * GPADH + acol) * 2);
            ldsm4(af[1], as_ + (uint32_t)((arow + 16) * GPADH + acol) * 2);
            #pragma unroll
            for (int p = 0; p < 4; p++) {
                uint32_t bm[4];
                int brow = wc * 64 + p * 16 + lrow;
                ldsm4(bm, bs_ + (uint32_t)(brow * GPADH + acol) * 2);
                uint32_t bf0[2] = { bm[0], bm[2] };
                uint32_t bf1[2] = { bm[1], bm[3] };
                mma_f16(acc[0][2 * p],     af[0], bf0);
                mma_f16(acc[1][2 * p],     af[1], bf0);
                mma_f16(acc[0][2 * p + 1], af[0], bf1);
                mma_f16(acc[1][2 * p + 1], af[1], bf1);
            }
        }
    };

    copy_tile(0, 0); CP_COMMIT();
    copy_tile(1, 1); CP_COMMIT();
    int buf = 0;
    for (int c = 0; c < NCH; c++) {
        CP_WAIT1();
        __syncthreads();
        if (c + 2 < NCH) copy_tile((buf + 2) % 3, c + 2);
        CP_COMMIT();
        compute(buf);
        buf = (buf + 1) % 3;
    }

    #pragma unroll
    for (int mt = 0; mt < 2; mt++) {
        int r = rowBase + wr * 32 + mt * 16 + (lane >> 2);
        #pragma unroll
        for (int nt = 0; nt < 8; nt++) {
            int col = colBase + wc * 64 + nt * 8 + 2 * j;
            float2 b2 = *(const float2*)&bias[col];
            float o00 = (acc[mt][nt][0] + b2.x) * osc, o01 = (acc[mt][nt][1] + b2.y) * osc;
            float o10 = (acc[mt][nt][2] + b2.x) * osc, o11 = (acc[mt][nt][3] + b2.y) * osc;
            if constexpr (sizeof(OutT) == 2) {
                *(uint32_t*)&C[(size_t)r * DIM + col]       = packf(o00, o01);
                *(uint32_t*)&C[(size_t)(r + 8) * DIM + col] = packf(o10, o11);
            } else {
                *(float2*)&C[(size_t)r * DIM + col]       = make_float2(o00, o01);
                *(float2*)&C[(size_t)(r + 8) * DIM + col] = make_float2(o10, o11);
            }
        }
    }
}

// ---------------- flash attention, fp16 mma + ldmatrix ------------------------
// Q pre-scaled (log2 domain); l accumulated via all-ones MMA column.
#define AQSH 72
#define QH    (128 * AQSH)                 // 9216 halves
#define KVSTH (64 * AQSH * 2)              // K+V stage halves
#define OFFK(b) (QH + (b) * KVSTH)
#define OFFV(b) (QH + (b) * KVSTH + 64 * AQSH)
#define ASMEM ((QH + 2 * KVSTH) * 2)       // 55296 bytes
#define NT    (SEQ / 64)

__global__ __launch_bounds__(256) void k_attn_h()
{
    extern __shared__ __half smh[];
    const uint32_t smb = smem_u32(smh);

    const int tid  = threadIdx.x;
    const int lane = tid & 31;
    const int wid  = tid >> 5;
    const int qt = blockIdx.x, h = blockIdx.y, b = blockIdx.z;
    const size_t qbase  = (size_t)(b * SEQ + qt * 128);
    const size_t kvbase = (size_t)(b * SEQ) * DIM + h * 64;

    const int lrow = lane & 15;
    const int lcol = (lane >> 4) << 3;
    const int vrow = ((lane >> 4) << 3) + (lane & 7);
    const int vcol = lane & 8;

    auto copy_q = [&]() {
        #pragma unroll
        for (int i = 0; i < 4; i++) {
            int idx = i * 256 + tid;
            int r = idx >> 3, c8 = idx & 7;
            cp16(smb + (r * AQSH + c8 * 8) * 2,
                 g_qh + (qbase + r) * DIM + h * 64 + c8 * 8);
        }
    };
    auto copy_kv = [&](int buf, int kt) {
        uint32_t kb = smb + OFFK(buf) * 2;
        uint32_t vb = smb + OFFV(buf) * 2;
        #pragma unroll
        for (int i = 0; i < 2; i++) {
            int idx = i * 256 + tid;
            int r = idx >> 3, c8 = idx & 7;
            size_t g = kvbase + (size_t)(kt * 64 + r) * DIM + c8 * 8;
            cp16(kb + (r * AQSH + c8 * 8) * 2, g_kh + g);
            cp16(vb + (r * AQSH + c8 * 8) * 2, g_vh + g);
        }
    };

    float Oa[8][4];
    #pragma unroll
    for (int nt = 0; nt < 8; nt++)
        #pragma unroll
        for (int q = 0; q < 4; q++) Oa[nt][q] = 0.f;
    float La[4] = {0.f, 0.f, 0.f, 0.f};              // row-sum accumulator
    float m0 = -1e30f, m1 = -1e30f;                  // log2 domain
    const uint32_t onesb[2] = {0x3C003C00u, 0x3C003C00u};

    copy_q(); copy_kv(0, 0); CP_COMMIT();
    CP_WAIT0(); __syncthreads();

    for (int kt = 0; kt < NT; kt++) {
        int bu = kt & 1;
        if (kt + 1 < NT) { copy_kv(bu ^ 1, kt + 1); CP_COMMIT(); }

        const uint32_t qb = smb;
        const uint32_t kb = smb + OFFK(bu) * 2;
        const uint32_t vb = smb + OFFV(bu) * 2;

        // ---- S = Q @ K^T (already log2-scaled via Q) ----
        float Sa[8][4];
        #pragma unroll
        for (int nt = 0; nt < 8; nt++)
            #pragma unroll
            for (int q = 0; q < 4; q++) Sa[nt][q] = 0.f;
        #pragma unroll
        for (int kk = 0; kk < 64; kk += 16) {
            uint32_t af[4];
            int arow = wid * 16 + lrow;
            int acol = kk + lcol;
            ldsm4(af, qb + (uint32_t)(arow * AQSH + acol) * 2);
            #pragma unroll
            for (int p = 0; p < 4; p++) {
                uint32_t bm[4];
                int brow = p * 16 + lrow;
                ldsm4(bm, kb + (uint32_t)(brow * AQSH + acol) * 2);
                uint32_t bf0[2] = { bm[0], bm[2] };
                uint32_t bf1[2] = { bm[1], bm[3] };
                mma_f16(Sa[2 * p],     af, bf0);
                mma_f16(Sa[2 * p + 1], af, bf1);
            }
        }

        // ---- online softmax (exp2 domain) ----
        float mx0 = m0, mx1 = m1;
        #pragma unroll
        for (int nt = 0; nt < 8; nt++) {
            mx0 = fmaxf(mx0, fmaxf(Sa[nt][0], Sa[nt][1]));
            mx1 = fmaxf(mx1, fmaxf(Sa[nt][2], Sa[nt][3]));
        }
        #pragma unroll
        for (int o = 1; o <= 2; o <<= 1) {
            mx0 = fmaxf(mx0, __shfl_xor_sync(0xffffffffu, mx0, o));
            mx1 = fmaxf(mx1, __shfl_xor_sync(0xffffffffu, mx1, o));
        }
        float corr0 = exp2f(m0 - mx0);
        float corr1 = exp2f(m1 - mx1);
        m0 = mx0; m1 = mx1;

        #pragma unroll
        for (int nt = 0; nt < 8; nt++) {
            Sa[nt][0] = exp2f(Sa[nt][0] - m0);
            Sa[nt][1] = exp2f(Sa[nt][1] - m0);
            Sa[nt][2] = exp2f(Sa[nt][2] - m1);
            Sa[nt][3] = exp2f(Sa[nt][3] - m1);
        }
        #pragma unroll
        for (int nt = 0; nt < 8; nt++) {
            Oa[nt][0] *= corr0; Oa[nt][1] *= corr0;
            Oa[nt][2] *= corr1; Oa[nt][3] *= corr1;
        }
        La[0] *= corr0; La[2] *= corr1;

        // ---- O += P @ V ; L += P @ 1 ----
        #pragma unroll
        for (int kk2 = 0; kk2 < 4; kk2++) {
            uint32_t af[4];
            af[0] = packf(Sa[2 * kk2][0],     Sa[2 * kk2][1]);
            af[1] = packf(Sa[2 * kk2][2],     Sa[2 * kk2][3]);
            af[2] = packf(Sa[2 * kk2 + 1][0], Sa[2 * kk2 + 1][1]);
            af[3] = packf(Sa[2 * kk2 + 1][2], Sa[2 * kk2 + 1][3]);
            mma_f16(La, af, onesb);
            int vr = kk2 * 16 + vrow;
            #pragma unroll
            for (int p = 0; p < 4; p++) {
                uint32_t vm[4];
                int vc = p * 16 + vcol;
                ldsm4t(vm, vb + (uint32_t)(vr * AQSH + vc) * 2);
                uint32_t bf0[2] = { vm[0], vm[2] };
                uint32_t bf1[2] = { vm[1], vm[3] };
                mma_f16(Oa[2 * p],     af, bf0);
                mma_f16(Oa[2 * p + 1], af, bf1);
            }
        }

        CP_WAIT0(); __syncthreads();
    }

    float inv0 = 1.f / La[0], inv1 = 1.f / La[2];
    size_t r = qbase + wid * 16 + (lane >> 2);
    #pragma unroll
    for (int nt = 0; nt < 8; nt++) {
        int col = h * 64 + nt * 8 + 2 * (lane & 3);
        *(uint32_t*)&g_ah[r * DIM + col] =
            packf(Oa[nt][0] * inv0, Oa[nt][1] * inv0);
        *(uint32_t*)&g_ah[(r + 8) * DIM + col] =
            packf(Oa[nt][2] * inv1, Oa[nt][3] * inv1);
    }
}

// ---------------- residual + layernorm ---------------------------------------
__global__ __launch_bounds__(256) void k_ln(const float* __restrict__ gamma,
                                            const float* __restrict__ beta,
                                            float* __restrict__ out)
{
    __shared__ float ws[8], wss[8];
    const int row = blockIdx.x;
    const int tid = threadIdx.x;

    const float4* p4 = (const float4*)(g_proj + (size_t)row * DIM);
    const float4* x4 = (const float4*)(g_xpe  + (size_t)row * DIM);
    float4 a = p4[tid];
    float4 b = x4[tid];
    float4 hv = make_float4(a.x + b.x, a.y + b.y, a.z + b.z, a.w + b.w);

    float s  = hv.x + hv.y + hv.z + hv.w;
    float ss = hv.x * hv.x + hv.y * hv.y + hv.z * hv.z + hv.w * hv.w;
    #pragma unroll
    for (int o = 16; o; o >>= 1) {
        s  += __shfl_xor_sync(0xffffffffu, s,  o);
        ss += __shfl_xor_sync(0xffffffffu, ss, o);
    }
    int w = tid >> 5;
    if ((tid & 31) == 0) { ws[w] = s; wss[w] = ss; }
    __syncthreads();

    float ts = 0.f, tss = 0.f;
    #pragma unroll
    for (int i = 0; i < 8; i++) { ts += ws[i]; tss += wss[i]; }
    float mean = ts * (1.f / 1024.f);
    float var  = tss * (1.f / 1024.f) - mean * mean;
    float rstd = rsqrtf(var + 1e-5f);

    float4 g  = ((const float4*)gamma)[tid];
    float4 be = ((const float4*)beta)[tid];
    float4 o;
    o.x = (hv.x - mean) * rstd * g.x + be.x;
    o.y = (hv.y - mean) * rstd * g.y + be.y;
    o.z = (hv.z - mean) * rstd * g.z + be.z;
    o.w = (hv.w - mean) * rstd * g.w + be.w;
    ((float4*)out)[(size_t)row * 256 + tid] = o;
}

// ---------------- launch ------------------------------------------------------
extern "C" void kernel_launch(void* const* d_in, const int* in_sizes, int n_in,
                              void* d_out, int out_size)
{
    const float* x     = (const float*)d_in[0];
    const float* wq    = (const float*)d_in[1];
    const float* bq    = (const float*)d_in[2];
    const float* wk    = (const float*)d_in[3];
    const float* bk    = (const float*)d_in[4];
    const float* wv    = (const float*)d_in[5];
    const float* bv    = (const float*)d_in[6];
    const float* wo    = (const float*)d_in[7];
    const float* bo    = (const float*)d_in[8];
    const float* gamma = (const float*)d_in[9];
    const float* beta  = (const float*)d_in[10];
    const float* pe    = (const float*)d_in[11];
    float* out = (float*)d_out;

    void *pxh, *pqh, *pkh, *pvh, *pah, *pproj, *pwTh;
    cudaGetSymbolAddress(&pxh,   g_xh);
    cudaGetSymbolAddress(&pqh,   g_qh);
    cudaGetSymbolAddress(&pkh,   g_kh);
    cudaGetSymbolAddress(&pvh,   g_vh);
    cudaGetSymbolAddress(&pah,   g_ah);
    cudaGetSymbolAddress(&pproj, g_proj);
    cudaGetSymbolAddress(&pwTh,  g_wTh);
    __half* wTh = (__half*)pwTh;

    cudaFuncSetAttribute(k_gemm_h<__half>, cudaFuncAttributeMaxDynamicSharedMemorySize, GSMEM);
    cudaFuncSetAttribute(k_gemm_h<float>,  cudaFuncAttributeMaxDynamicSharedMemorySize, GSMEM);
    cudaFuncSetAttribute(k_attn_h, cudaFuncAttributeMaxDynamicSharedMemorySize, ASMEM);

    k_addpe<<<(NTOK * DIM / 4) / 256, 256>>>(x, pe);

    dim3 tgrid(DIM / 32, DIM / 32, 4);
    k_transpose4<<<tgrid, 256>>>(wq, wk, wv, wo);

    // fused QKV: grid.z = 3; Q output pre-scaled by SCL
    dim3 qkvgrid(DIM / 128, NTOK / 128, 3);      // (8, 64, 3)
    k_gemm_h<__half><<<qkvgrid, 256, GSMEM>>>(
        (const __half*)pxh,
        wTh + 0 * DIM * DIM, wTh + 1 * DIM * DIM, wTh + 2 * DIM * DIM,
        bq, bk, bv,
        (__half*)pqh, (__half*)pkh, (__half*)pvh,
        SCL);

    dim3 agrid(SEQ / 128, NH, BATCH);            // (16, 16, 4)
    k_attn_h<<<agrid, 256, ASMEM>>>();

    dim3 ogrid(DIM / 128, NTOK / 128, 1);
    k_gemm_h<float><<<ogrid, 256, GSMEM>>>(
        (const __half*)pah,
        wTh + 3 * DIM * DIM, wTh + 3 * DIM * DIM, wTh + 3 * DIM * DIM,
        bo, bo, bo,
        (float*)pproj, (float*)pproj, (float*)pproj,
        1.f);

    k_ln<<<NTOK, 256>>>(gamma, beta, out);
}

// round 13
// speedup vs baseline: 1.3371x; 1.0462x over previous
#include <cuda_runtime.h>
#include <cuda_fp16.h>
#include <cstdint>

#define SEQ   2048
#define BATCH 4
#define NTOK  (SEQ * BATCH)      // 8192
#define DIM   1024
#define NH    16
#define HD    64

// ---------------- scratch (device globals per allocation rules) -------------
__device__ float  g_xpe [NTOK * DIM];     // fp32 residual for LN
__device__ float  g_proj[NTOK * DIM];     // fp32 O-projection for LN
__device__ __half g_xh  [NTOK * DIM];     // half x+pe (GEMM A)
__device__ __half g_qh  [NTOK * DIM];     // pre-scaled by 0.125*log2(e)
__device__ __half g_kh  [NTOK * DIM];
__device__ __half g_vh  [NTOK * DIM];
__device__ __half g_ah  [NTOK * DIM];     // attention output (half)
__device__ __half g_wTh [4][DIM * DIM];   // transposed weights [N][K], half

#define SCL 0.18033688011112042f          // 0.125 * log2(e)

// ---------------- helpers -----------------------------------------------------
__device__ __forceinline__ uint32_t smem_u32(const void* p) {
    uint32_t a;
    asm("{ .reg .u64 t; cvta.to.shared.u64 t, %1; cvt.u32.u64 %0, t; }" : "=r"(a) : "l"(p));
    return a;
}
__device__ __forceinline__ void cp16(uint32_t dst, const void* src) {
    asm volatile("cp.async.cg.shared.global [%0], [%1], 16;" :: "r"(dst), "l"(src));
}
#define CP_COMMIT() asm volatile("cp.async.commit_group;" ::: "memory")
#define CP_WAIT0()  asm volatile("cp.async.wait_group 0;" ::: "memory")
#define CP_WAIT1()  asm volatile("cp.async.wait_group 1;" ::: "memory")

__device__ __forceinline__ void mma_f16(float* d, const uint32_t* a, const uint32_t* b) {
    asm volatile(
        "mma.sync.aligned.m16n8k16.row.col.f32.f16.f16.f32 "
        "{%0,%1,%2,%3}, {%4,%5,%6,%7}, {%8,%9}, {%0,%1,%2,%3};\n"
        : "+f"(d[0]), "+f"(d[1]), "+f"(d[2]), "+f"(d[3])
        : "r"(a[0]), "r"(a[1]), "r"(a[2]), "r"(a[3]), "r"(b[0]), "r"(b[1]));
}
__device__ __forceinline__ void ldsm4(uint32_t* r, uint32_t addr) {
    asm volatile("ldmatrix.sync.aligned.m8n8.x4.shared.b16 {%0,%1,%2,%3}, [%4];"
        : "=r"(r[0]), "=r"(r[1]), "=r"(r[2]), "=r"(r[3]) : "r"(addr));
}
__device__ __forceinline__ void ldsm4t(uint32_t* r, uint32_t addr) {
    asm volatile("ldmatrix.sync.aligned.m8n8.x4.trans.shared.b16 {%0,%1,%2,%3}, [%4];"
        : "=r"(r[0]), "=r"(r[1]), "=r"(r[2]), "=r"(r[3]) : "r"(addr));
}
__device__ __forceinline__ uint32_t packf(float x, float y) {
    __half2 t = __floats2half2_rn(x, y);
    return *(uint32_t*)&t;
}

// ---------------- x + pe (fp32 out + half out) -------------------------------
__global__ void k_addpe(const float* __restrict__ x, const float* __restrict__ pe) {
    int idx = blockIdx.x * 256 + threadIdx.x;        // float4 index
    const float4* x4  = (const float4*)x;
    const float4* pe4 = (const float4*)pe;
    float4*       o4  = (float4*)g_xpe;
    int row = idx >> 8;
    int c   = idx & 255;
    int s   = row & (SEQ - 1);
    float4 a = x4[idx];
    float4 b = pe4[s * 256 + c];
    a.x += b.x; a.y += b.y; a.z += b.z; a.w += b.w;
    o4[idx] = a;
    uint2 hp;
    hp.x = packf(a.x, a.y);
    hp.y = packf(a.z, a.w);
    *(uint2*)&g_xh[(size_t)idx * 4] = hp;
}

// ---------------- fused weight transpose -> half ------------------------------
__global__ __launch_bounds__(256) void k_transpose4(
    const float* __restrict__ w0, const float* __restrict__ w1,
    const float* __restrict__ w2, const float* __restrict__ w3)
{
    __shared__ float t[32][33];
    const float* in;
    switch (blockIdx.z) {
        case 0: in = w0; break;
        case 1: in = w1; break;
        case 2: in = w2; break;
        default: in = w3; break;
    }
    __half* out = g_wTh[blockIdx.z];
    int n0 = blockIdx.x * 32, k0 = blockIdx.y * 32;
    int tx = threadIdx.x & 31, ty = threadIdx.x >> 5;
    #pragma unroll
    for (int i = ty; i < 32; i += 8)
        t[i][tx] = in[(size_t)(k0 + i) * DIM + n0 + tx];
    __syncthreads();
    #pragma unroll
    for (int i = ty; i < 32; i += 8)
        out[(size_t)(n0 + i) * DIM + k0 + tx] = __float2half(t[tx][i]);
}

// ---------------- fp16 mma GEMM: C[M,N] = (A @ BtT + bias) * osc -------------
#define GPADH 72
#define TILEH (128 * GPADH)
#define STAGEB (2 * TILEH * 2)              // 36864
#define GSMEM (3 * STAGEB)                  // 110592
#define NCH   (DIM / 64)

template <typename OutT>
__global__ __launch_bounds__(256) void k_gemm_h(
    const __half* __restrict__ A,
    const __half* __restrict__ Bt0, const __half* __restrict__ Bt1, const __half* __restrict__ Bt2,
    const float* __restrict__ bi0,  const float* __restrict__ bi1,  const float* __restrict__ bi2,
    OutT* __restrict__ C0, OutT* __restrict__ C1, OutT* __restrict__ C2,
    float qscale)
{
    extern __shared__ __half smh[];
    const uint32_t smb = smem_u32(smh);
    const int tid  = threadIdx.x;
    const int lane = tid & 31;
    const int wid  = tid >> 5;
    const int wr   = wid & 3;
    const int wc   = wid >> 2;
    const int j    = lane & 3;
    const int rowBase = blockIdx.y * 128;
    const int colBase = blockIdx.x * 128;

    const __half* Bt   = (blockIdx.z == 0) ? Bt0 : (blockIdx.z == 1) ? Bt1 : Bt2;
    const float*  bias = (blockIdx.z == 0) ? bi0 : (blockIdx.z == 1) ? bi1 : bi2;
    OutT*         C    = (blockIdx.z == 0) ? C0  : (blockIdx.z == 1) ? C1  : C2;
    const float   osc  = (blockIdx.z == 0) ? qscale : 1.f;

    const __half* Ab = A  + (size_t)rowBase * DIM;
    const __half* Bb = Bt + (size_t)colBase * DIM;

    const int lrow = lane & 15;
    const int lcol = (lane >> 4) << 3;

    float acc[2][8][4];
    #pragma unroll
    for (int mt = 0; mt < 2; mt++)
        #pragma unroll
        for (int nt = 0; nt < 8; nt++)
            #pragma unroll
            for (int q = 0; q < 4; q++) acc[mt][nt][q] = 0.f;

    auto copy_tile = [&](int buf, int chunk) {
        uint32_t as_ = smb + buf * STAGEB;
        uint32_t bs_ = as_ + TILEH * 2;
        #pragma unroll
        for (int i = 0; i < 4; i++) {
            int idx = i * 256 + tid;
            int r = idx >> 3, c8 = idx & 7;
            uint32_t off = (r * GPADH + c8 * 8) * 2;
            cp16(as_ + off, Ab + (size_t)r * DIM + chunk * 64 + c8 * 8);
            cp16(bs_ + off, Bb + (size_t)r * DIM + chunk * 64 + c8 * 8);
        }
    };
    auto compute = [&](int buf) {
        const uint32_t as_ = smb + buf * STAGEB;
        const uint32_t bs_ = as_ + TILEH * 2;
        #pragma unroll
        for (int kk = 0; kk < 64; kk += 16) {
            uint32_t af[2][4];
            int arow = wr * 32 + lrow;
            int acol = kk + lcol;
            ldsm4(af[0], as_ + (uint32_t)(arow * GPADH + acol) * 2);
            ldsm4(af[1], as_ + (uint32_t)((arow + 16) * GPADH + acol) * 2);
            #pragma unroll
            for (int p = 0; p < 4; p++) {
                uint32_t bm[4];
                int brow = wc * 64 + p * 16 + lrow;
                ldsm4(bm, bs_ + (uint32_t)(brow * GPADH + acol) * 2);
                uint32_t bf0[2] = { bm[0], bm[2] };
                uint32_t bf1[2] = { bm[1], bm[3] };
                mma_f16(acc[0][2 * p],     af[0], bf0);
                mma_f16(acc[1][2 * p],     af[1], bf0);
                mma_f16(acc[0][2 * p + 1], af[0], bf1);
                mma_f16(acc[1][2 * p + 1], af[1], bf1);
            }
        }
    };

    copy_tile(0, 0); CP_COMMIT();
    copy_tile(1, 1); CP_COMMIT();
    int buf = 0;
    for (int c = 0; c < NCH; c++) {
        CP_WAIT1();
        __syncthreads();
        if (c + 2 < NCH) copy_tile((buf + 2) % 3, c + 2);
        CP_COMMIT();
        compute(buf);
        buf = (buf + 1) % 3;
    }

    #pragma unroll
    for (int mt = 0; mt < 2; mt++) {
        int r = rowBase + wr * 32 + mt * 16 + (lane >> 2);
        #pragma unroll
        for (int nt = 0; nt < 8; nt++) {
            int col = colBase + wc * 64 + nt * 8 + 2 * j;
            float2 b2 = *(const float2*)&bias[col];
            float o00 = (acc[mt][nt][0] + b2.x) * osc, o01 = (acc[mt][nt][1] + b2.y) * osc;
            float o10 = (acc[mt][nt][2] + b2.x) * osc, o11 = (acc[mt][nt][3] + b2.y) * osc;
            if constexpr (sizeof(OutT) == 2) {
                *(uint32_t*)&C[(size_t)r * DIM + col]       = packf(o00, o01);
                *(uint32_t*)&C[(size_t)(r + 8) * DIM + col] = packf(o10, o11);
            } else {
                *(float2*)&C[(size_t)r * DIM + col]       = make_float2(o00, o01);
                *(float2*)&C[(size_t)(r + 8) * DIM + col] = make_float2(o10, o11);
            }
        }
    }
}

// ---------------- flash attention: 4 warps x 32 q-rows, fat warp tile ---------
// 128 threads; warp owns 32 q-rows x 64 keys. K/V frags loaded ONCE per warp,
// reused by both m-frags. Q pre-scaled (log2); l via ones-column MMA.
#define AQSH 72
#define QH    (128 * AQSH)                 // 9216 halves
#define KVSTH (64 * AQSH * 2)              // K+V stage halves
#define OFFK(b) (QH + (b) * KVSTH)
#define OFFV(b) (QH + (b) * KVSTH + 64 * AQSH)
#define ASMEM ((QH + 2 * KVSTH) * 2)       // 55296 bytes
#define NT    (SEQ / 64)

__global__ __launch_bounds__(128) void k_attn_h()
{
    extern __shared__ __half smh[];
    const uint32_t smb = smem_u32(smh);

    const int tid  = threadIdx.x;
    const int lane = tid & 31;
    const int wid  = tid >> 5;               // 0..3
    const int qt = blockIdx.x, h = blockIdx.y, b = blockIdx.z;
    const size_t qbase  = (size_t)(b * SEQ + qt * 128);
    const size_t kvbase = (size_t)(b * SEQ) * DIM + h * 64;

    const int lrow = lane & 15;
    const int lcol = (lane >> 4) << 3;
    const int vrow = ((lane >> 4) << 3) + (lane & 7);
    const int vcol = lane & 8;

    auto copy_q = [&]() {
        #pragma unroll
        for (int i = 0; i < 8; i++) {
            int idx = i * 128 + tid;         // 1024 chunks
            int r = idx >> 3, c8 = idx & 7;
            cp16(smb + (r * AQSH + c8 * 8) * 2,
                 g_qh + (qbase + r) * DIM + h * 64 + c8 * 8);
        }
    };
    auto copy_kv = [&](int buf, int kt) {
        uint32_t kb = smb + OFFK(buf) * 2;
        uint32_t vb = smb + OFFV(buf) * 2;
        #pragma unroll
        for (int i = 0; i < 4; i++) {
            int idx = i * 128 + tid;         // 512 chunks
            int r = idx >> 3, c8 = idx & 7;
            size_t g = kvbase + (size_t)(kt * 64 + r) * DIM + c8 * 8;
            cp16(kb + (r * AQSH + c8 * 8) * 2, g_kh + g);
            cp16(vb + (r * AQSH + c8 * 8) * 2, g_vh + g);
        }
    };

    float Oa[2][8][4];
    #pragma unroll
    for (int mt = 0; mt < 2; mt++)
        #pragma unroll
        for (int nt = 0; nt < 8; nt++)
            #pragma unroll
            for (int q = 0; q < 4; q++) Oa[mt][nt][q] = 0.f;
    float La[2][4];
    #pragma unroll
    for (int mt = 0; mt < 2; mt++)
        #pragma unroll
        for (int q = 0; q < 4; q++) La[mt][q] = 0.f;
    float m[2][2] = {{-1e30f, -1e30f}, {-1e30f, -1e30f}};   // log2 domain
    const uint32_t onesb[2] = {0x3C003C00u, 0x3C003C00u};

    copy_q(); copy_kv(0, 0); CP_COMMIT();
    CP_WAIT0(); __syncthreads();

    for (int kt = 0; kt < NT; kt++) {
        int bu = kt & 1;
        if (kt + 1 < NT) { copy_kv(bu ^ 1, kt + 1); CP_COMMIT(); }

        const uint32_t qb = smb;
        const uint32_t kb = smb + OFFK(bu) * 2;
        const uint32_t vb = smb + OFFV(bu) * 2;

        // ---- S = Q @ K^T : K frags loaded once, used by both m-frags ----
        float Sa[2][8][4];
        #pragma unroll
        for (int mt = 0; mt < 2; mt++)
            #pragma unroll
            for (int nt = 0; nt < 8; nt++)
                #pragma unroll
                for (int q = 0; q < 4; q++) Sa[mt][nt][q] = 0.f;
        #pragma unroll
        for (int kk = 0; kk < 64; kk += 16) {
            uint32_t af[2][4];
            int arow = wid * 32 + lrow;
            int acol = kk + lcol;
            ldsm4(af[0], qb + (uint32_t)(arow * AQSH + acol) * 2);
            ldsm4(af[1], qb + (uint32_t)((arow + 16) * AQSH + acol) * 2);
            #pragma unroll
            for (int p = 0; p < 4; p++) {
                uint32_t bm[4];
                int brow = p * 16 + lrow;
                ldsm4(bm, kb + (uint32_t)(brow * AQSH + acol) * 2);
                uint32_t bf0[2] = { bm[0], bm[2] };
                uint32_t bf1[2] = { bm[1], bm[3] };
                mma_f16(Sa[0][2 * p],     af[0], bf0);
                mma_f16(Sa[1][2 * p],     af[1], bf0);
                mma_f16(Sa[0][2 * p + 1], af[0], bf1);
                mma_f16(Sa[1][2 * p + 1], af[1], bf1);
            }
        }

        // ---- online softmax (exp2 domain), per m-frag ----
        #pragma unroll
        for (int mt = 0; mt < 2; mt++) {
            float mx0 = m[mt][0], mx1 = m[mt][1];
            #pragma unroll
            for (int nt = 0; nt < 8; nt++) {
                mx0 = fmaxf(mx0, fmaxf(Sa[mt][nt][0], Sa[mt][nt][1]));
                mx1 = fmaxf(mx1, fmaxf(Sa[mt][nt][2], Sa[mt][nt][3]));
            }
            #pragma unroll
            for (int o = 1; o <= 2; o <<= 1) {
                mx0 = fmaxf(mx0, __shfl_xor_sync(0xffffffffu, mx0, o));
                mx1 = fmaxf(mx1, __shfl_xor_sync(0xffffffffu, mx1, o));
            }
            float corr0 = exp2f(m[mt][0] - mx0);
            float corr1 = exp2f(m[mt][1] - mx1);
            m[mt][0] = mx0; m[mt][1] = mx1;
            #pragma unroll
            for (int nt = 0; nt < 8; nt++) {
                Sa[mt][nt][0] = exp2f(Sa[mt][nt][0] - mx0);
                Sa[mt][nt][1] = exp2f(Sa[mt][nt][1] - mx0);
                Sa[mt][nt][2] = exp2f(Sa[mt][nt][2] - mx1);
                Sa[mt][nt][3] = exp2f(Sa[mt][nt][3] - mx1);
            }
            #pragma unroll
            for (int nt = 0; nt < 8; nt++) {
                Oa[mt][nt][0] *= corr0; Oa[mt][nt][1] *= corr0;
                Oa[mt][nt][2] *= corr1; Oa[mt][nt][3] *= corr1;
            }
            La[mt][0] *= corr0; La[mt][2] *= corr1;
        }

        // ---- O += P @ V ; L += P @ 1 : V frags loaded once per warp ----
        #pragma unroll
        for (int kk2 = 0; kk2 < 4; kk2++) {
            uint32_t af[2][4];
            #pragma unroll
            for (int mt = 0; mt < 2; mt++) {
                af[mt][0] = packf(Sa[mt][2 * kk2][0],     Sa[mt][2 * kk2][1]);
                af[mt][1] = packf(Sa[mt][2 * kk2][2],     Sa[mt][2 * kk2][3]);
                af[mt][2] = packf(Sa[mt][2 * kk2 + 1][0], Sa[mt][2 * kk2 + 1][1]);
                af[mt][3] = packf(Sa[mt][2 * kk2 + 1][2], Sa[mt][2 * kk2 + 1][3]);
                mma_f16(La[mt], af[mt], onesb);
            }
            int vr = kk2 * 16 + vrow;
            #pragma unroll
            for (int p = 0; p < 4; p++) {
                uint32_t vm[4];
                int vc = p * 16 + vcol;
                ldsm4t(vm, vb + (uint32_t)(vr * AQSH + vc) * 2);
                uint32_t bf0[2] = { vm[0], vm[2] };
                uint32_t bf1[2] = { vm[1], vm[3] };
                mma_f16(Oa[0][2 * p],     af[0], bf0);
                mma_f16(Oa[1][2 * p],     af[1], bf0);
                mma_f16(Oa[0][2 * p + 1], af[0], bf1);
                mma_f16(Oa[1][2 * p + 1], af[1], bf1);
            }
        }

        CP_WAIT0(); __syncthreads();
    }

    #pragma unroll
    for (int mt = 0; mt < 2; mt++) {
        float inv0 = 1.f / La[mt][0], inv1 = 1.f / La[mt][2];
        size_t r = qbase + wid * 32 + mt * 16 + (lane >> 2);
        #pragma unroll
        for (int nt = 0; nt < 8; nt++) {
            int col = h * 64 + nt * 8 + 2 * (lane & 3);
            *(uint32_t*)&g_ah[r * DIM + col] =
                packf(Oa[mt][nt][0] * inv0, Oa[mt][nt][1] * inv0);
            *(uint32_t*)&g_ah[(r + 8) * DIM + col] =
                packf(Oa[mt][nt][2] * inv1, Oa[mt][nt][3] * inv1);
        }
    }
}

// ---------------- residual + layernorm ---------------------------------------
__global__ __launch_bounds__(256) void k_ln(const float* __restrict__ gamma,
                                            const float* __restrict__ beta,
                                            float* __restrict__ out)
{
    __shared__ float ws[8], wss[8];
    const int row = blockIdx.x;
    const int tid = threadIdx.x;

    const float4* p4 = (const float4*)(g_proj + (size_t)row * DIM);
    const float4* x4 = (const float4*)(g_xpe  + (size_t)row * DIM);
    float4 a = p4[tid];
    float4 b = x4[tid];
    float4 hv = make_float4(a.x + b.x, a.y + b.y, a.z + b.z, a.w + b.w);

    float s  = hv.x + hv.y + hv.z + hv.w;
    float ss = hv.x * hv.x + hv.y * hv.y + hv.z * hv.z + hv.w * hv.w;
    #pragma unroll
    for (int o = 16; o; o >>= 1) {
        s  += __shfl_xor_sync(0xffffffffu, s,  o);
        ss += __shfl_xor_sync(0xffffffffu, ss, o);
    }
    int w = tid >> 5;
    if ((tid & 31) == 0) { ws[w] = s; wss[w] = ss; }
    __syncthreads();

    float ts = 0.f, tss = 0.f;
    #pragma unroll
    for (int i = 0; i < 8; i++) { ts += ws[i]; tss += wss[i]; }
    float mean = ts * (1.f / 1024.f);
    float var  = tss * (1.f / 1024.f) - mean * mean;
    float rstd = rsqrtf(var + 1e-5f);

    float4 g  = ((const float4*)gamma)[tid];
    float4 be = ((const float4*)beta)[tid];
    float4 o;
    o.x = (hv.x - mean) * rstd * g.x + be.x;
    o.y = (hv.y - mean) * rstd * g.y + be.y;
    o.z = (hv.z - mean) * rstd * g.z + be.z;
    o.w = (hv.w - mean) * rstd * g.w + be.w;
    ((float4*)out)[(size_t)row * 256 + tid] = o;
}

// ---------------- launch ------------------------------------------------------
extern "C" void kernel_launch(void* const* d_in, const int* in_sizes, int n_in,
                              void* d_out, int out_size)
{
    const float* x     = (const float*)d_in[0];
    const float* wq    = (const float*)d_in[1];
    const float* bq    = (const float*)d_in[2];
    const float* wk    = (const float*)d_in[3];
    const float* bk    = (const float*)d_in[4];
    const float* wv    = (const float*)d_in[5];
    const float* bv    = (const float*)d_in[6];
    const float* wo    = (const float*)d_in[7];
    const float* bo    = (const float*)d_in[8];
    const float* gamma = (const float*)d_in[9];
    const float* beta  = (const float*)d_in[10];
    const float* pe    = (const float*)d_in[11];
    float* out = (float*)d_out;

    void *pxh, *pqh, *pkh, *pvh, *pah, *pproj, *pwTh;
    cudaGetSymbolAddress(&pxh,   g_xh);
    cudaGetSymbolAddress(&pqh,   g_qh);
    cudaGetSymbolAddress(&pkh,   g_kh);
    cudaGetSymbolAddress(&pvh,   g_vh);
    cudaGetSymbolAddress(&pah,   g_ah);
    cudaGetSymbolAddress(&pproj, g_proj);
    cudaGetSymbolAddress(&pwTh,  g_wTh);
    __half* wTh = (__half*)pwTh;

    cudaFuncSetAttribute(k_gemm_h<__half>, cudaFuncAttributeMaxDynamicSharedMemorySize, GSMEM);
    cudaFuncSetAttribute(k_gemm_h<float>,  cudaFuncAttributeMaxDynamicSharedMemorySize, GSMEM);
    cudaFuncSetAttribute(k_attn_h, cudaFuncAttributeMaxDynamicSharedMemorySize, ASMEM);

    k_addpe<<<(NTOK * DIM / 4) / 256, 256>>>(x, pe);

    dim3 tgrid(DIM / 32, DIM / 32, 4);
    k_transpose4<<<tgrid, 256>>>(wq, wk, wv, wo);

    dim3 qkvgrid(DIM / 128, NTOK / 128, 3);      // (8, 64, 3)
    k_gemm_h<__half><<<qkvgrid, 256, GSMEM>>>(
        (const __half*)pxh,
        wTh + 0 * DIM * DIM, wTh + 1 * DIM * DIM, wTh + 2 * DIM * DIM,
        bq, bk, bv,
        (__half*)pqh, (__half*)pkh, (__half*)pvh,
        SCL);

    dim3 agrid(SEQ / 128, NH, BATCH);            // (16, 16, 4)
    k_attn_h<<<agrid, 128, ASMEM>>>();

    dim3 ogrid(DIM / 128, NTOK / 128, 1);
    k_gemm_h<float><<<ogrid, 256, GSMEM>>>(
        (const __half*)pah,
        wTh + 3 * DIM * DIM, wTh + 3 * DIM * DIM, wTh + 3 * DIM * DIM,
        bo, bo, bo,
        (float*)pproj, (float*)pproj, (float*)pproj,
        1.f);

    k_ln<<<NTOK, 256>>>(gamma, beta, out);
}